// round 2
// baseline (speedup 1.0000x reference)
#include <cuda_runtime.h>
#include <math.h>

#define BB 2048
#define NN 256
#define MM 64
#define UU 512
#define INP 10
#define CLIPV 20.0f

#define KCAT 1040   // 10 + 512 + 512 = 1034, padded to mult of 16
#define ZN 2048
#define RWN 268     // 70 + 198
#define RWNPAD 384
#define XON 576     // 512 + 64

// ---------------- scratch (device globals, no allocation) ----------------
__device__ float g_hprep[BB * UU];
__device__ float g_xcat[(size_t)BB * KCAT];
__device__ float g_wcat[(size_t)KCAT * ZN];
__device__ float g_z[(size_t)BB * ZN];
__device__ float g_h[BB * UU];
__device__ float g_wrw[UU * RWNPAD];
__device__ float g_brw[RWNPAD];
__device__ float g_rw[(size_t)BB * RWN];
__device__ float g_xo[(size_t)BB * XON];

// ---------------- helpers ----------------
__device__ __forceinline__ float sigm(float x) { return 1.0f / (1.0f + expf(-x)); }
__device__ __forceinline__ float softplus(float x) {
    return (x > 20.0f) ? x : log1pf(expf(x));
}

__device__ __forceinline__ float blockReduceSum(float v, volatile float* red) {
    #pragma unroll
    for (int o = 16; o; o >>= 1) v += __shfl_xor_sync(0xffffffffu, v, o);
    if ((threadIdx.x & 31) == 0) red[threadIdx.x >> 5] = v;
    __syncthreads();
    if (threadIdx.x == 0) {
        float s = 0.f;
        #pragma unroll
        for (int i = 0; i < 8; i++) s += red[i];
        red[0] = s;
    }
    __syncthreads();
    float r = red[0];
    __syncthreads();
    return r;
}

__device__ __forceinline__ float blockReduceMax(float v, volatile float* red) {
    #pragma unroll
    for (int o = 16; o; o >>= 1) v = fmaxf(v, __shfl_xor_sync(0xffffffffu, v, o));
    if ((threadIdx.x & 31) == 0) red[threadIdx.x >> 5] = v;
    __syncthreads();
    if (threadIdx.x == 0) {
        float s = red[0];
        #pragma unroll
        for (int i = 1; i < 8; i++) s = fmaxf(s, red[i]);
        red[0] = s;
    }
    __syncthreads();
    float r = red[0];
    __syncthreads();
    return r;
}

// ---------------- generic tiled SGEMM: C = A(MxK) * B(KxN) + bias ----------------
template<int BM, int BN, int BK, int TM, int TN>
__global__ __launch_bounds__((BM / TM) * (BN / TN))
void sgemm(const float* __restrict__ A, const float* __restrict__ Bm,
           const float* __restrict__ bias, float* __restrict__ C,
           int Kdim, int lda, int ldb, int ldc, int Nreal, float clipv)
{
    constexpr int THREADS = (BM / TM) * (BN / TN);
    __shared__ float As[BK][BM + 4];
    __shared__ float Bs[BK][BN];
    const int tid = threadIdx.x;
    const int brow = blockIdx.y * BM;
    const int bcol = blockIdx.x * BN;
    const int tx = tid % (BN / TN);
    const int ty = tid / (BN / TN);

    float acc[TM][TN];
    #pragma unroll
    for (int i = 0; i < TM; i++)
        #pragma unroll
        for (int j = 0; j < TN; j++) acc[i][j] = 0.f;

    for (int k0 = 0; k0 < Kdim; k0 += BK) {
        #pragma unroll
        for (int l = 0; l < BM * BK / (THREADS * 4); l++) {
            int idx = (tid + l * THREADS) * 4;
            int r = idx / BK, c = idx % BK;
            float4 v = *(const float4*)(A + (size_t)(brow + r) * lda + k0 + c);
            As[c + 0][r] = v.x; As[c + 1][r] = v.y;
            As[c + 2][r] = v.z; As[c + 3][r] = v.w;
        }
        #pragma unroll
        for (int l = 0; l < BK * BN / (THREADS * 4); l++) {
            int idx = (tid + l * THREADS) * 4;
            int r = idx / BN, c = idx % BN;
            *(float4*)(&Bs[r][c]) = *(const float4*)(Bm + (size_t)(k0 + r) * ldb + bcol + c);
        }
        __syncthreads();
        #pragma unroll
        for (int k = 0; k < BK; k++) {
            float af[TM], bf[TN];
            #pragma unroll
            for (int i = 0; i < TM; i++) af[i] = As[k][ty * TM + i];
            #pragma unroll
            for (int j = 0; j < TN; j++) bf[j] = Bs[k][tx * TN + j];
            #pragma unroll
            for (int i = 0; i < TM; i++)
                #pragma unroll
                for (int j = 0; j < TN; j++) acc[i][j] += af[i] * bf[j];
        }
        __syncthreads();
    }

    #pragma unroll
    for (int i = 0; i < TM; i++) {
        int grow = brow + ty * TM + i;
        #pragma unroll
        for (int j = 0; j < TN; j++) {
            int gcol = bcol + tx * TN + j;
            if (gcol < Nreal) {
                float v = acc[i][j] + bias[gcol];
                if (clipv > 0.f) v = fminf(fmaxf(v, -clipv), clipv);
                C[(size_t)grow * ldc + gcol] = v;
            }
        }
    }
}

// ---------------- build / pointwise kernels ----------------
__global__ void build_wcat(const float* __restrict__ Wx, const float* __restrict__ Wh) {
    int idx = blockIdx.x * 256 + threadIdx.x;
    if (idx >= KCAT * ZN) return;
    int r = idx / ZN, c = idx % ZN;
    float v = 0.f;
    if (r < 522) v = Wx[r * ZN + c];
    else if (r < 1034) v = Wh[(r - 522) * ZN + c];
    g_wcat[idx] = v;
}

__global__ void build_xcat(const float* __restrict__ x_t, const float* __restrict__ H0) {
    int idx = blockIdx.x * 256 + threadIdx.x;
    if (idx >= BB * KCAT) return;
    int b = idx / KCAT, c = idx % KCAT;
    float v = 0.f;
    if (c < INP) v = x_t[b * INP + c];
    else if (c < 522) v = g_hprep[b * UU + (c - INP)];
    else if (c < 1034) v = H0[b * UU + (c - 522)];
    g_xcat[idx] = v;
}

__global__ void build_wrw(const float* __restrict__ Wr, const float* __restrict__ Ww,
                          const float* __restrict__ br, const float* __restrict__ bw) {
    int idx = blockIdx.x * 256 + threadIdx.x;
    if (idx < RWNPAD) {
        float bv = 0.f;
        if (idx < 70) bv = br[idx];
        else if (idx < RWN) bv = bw[idx - 70];
        g_brw[idx] = bv;
    }
    if (idx >= UU * RWNPAD) return;
    int r = idx / RWNPAD, c = idx % RWNPAD;
    float v = 0.f;
    if (c < 70) v = Wr[r * 70 + c];
    else if (c < RWN) v = Ww[r * 198 + (c - 70)];
    g_wrw[idx] = v;
}

__global__ void gates_kernel(const float* __restrict__ C0) {
    int idx = blockIdx.x * 256 + threadIdx.x;
    if (idx >= BB * UU) return;
    int b = idx / UU, u = idx % UU;
    const float* zr = g_z + (size_t)b * ZN;
    float gi = zr[u], gf = zr[u + 512], gg = zr[u + 1024], go = zr[u + 1536];
    float c = sigm(gf) * C0[idx] + sigm(gi) * tanhf(gg);
    float h = sigm(go) * tanhf(c);
    h = fminf(fmaxf(h, -CLIPV), CLIPV);
    g_h[idx] = h;
}

__global__ void build_xo(const float* __restrict__ Rt) {
    int idx = blockIdx.x * 256 + threadIdx.x;
    if (idx >= BB * XON) return;
    int b = idx / XON, c = idx % XON;
    g_xo[idx] = (c < UU) ? g_h[b * UU + c] : Rt[b * MM + (c - UU)];
}

// ---------------- NTM addressing + memory update (one CTA per batch row) ----------------
#define ADDR_SMEM_FLOATS (16640 + 256 + 64 + 256 + 256 + 256 + 64 + 64 + 32 + 8)

__global__ __launch_bounds__(256)
void ntm_addr_kernel(const float* __restrict__ m0, const float* __restrict__ A0,
                     float* __restrict__ out_mt, float* __restrict__ out_Rt,
                     float* __restrict__ out_wr, float* __restrict__ out_ww)
{
    extern __shared__ float sm[];
    float* m0s    = sm;
    float* mnorm  = sm + 16640;
    float* ks     = mnorm + 256;
    float* wgs    = ks + 64;
    float* wread  = wgs + 256;
    float* wwrite = wread + 256;
    float* delv   = wwrite + 256;
    float* addv   = delv + 64;
    float* red    = addv + 64;
    float* scal   = red + 32;

    const int b = blockIdx.x;
    const int tid = threadIdx.x;
    const float* m0g = m0 + (size_t)b * (NN * MM);

    for (int e = tid; e < NN * MM; e += 256)
        m0s[(e >> 6) * 65 + (e & 63)] = m0g[e];
    __syncthreads();

    {
        float s = 0.f;
        #pragma unroll 8
        for (int m = 0; m < MM; m++) { float v = m0s[tid * 65 + m]; s += v * v; }
        mnorm[tid] = sqrtf(s);
    }

    const float* rwrow = g_rw + (size_t)b * RWN;

    for (int hd = 0; hd < 2; hd++) {
        const float* head = rwrow + (hd ? 70 : 0);
        if (tid < 64) ks[tid] = tanhf(head[tid]);
        if (tid == 64) {
            scal[0] = softplus(head[64]);
            scal[1] = sigm(head[65]);
            float a = head[66], bq = head[67], cq = head[68];
            float mx = fmaxf(a, fmaxf(bq, cq));
            float e0 = expf(a - mx), e1 = expf(bq - mx), e2 = expf(cq - mx);
            float se = e0 + e1 + e2;
            scal[2] = e0 / se; scal[3] = e1 / se; scal[4] = e2 / se;
            scal[5] = softplus(head[69]);
        }
        __syncthreads();

        float kv = (tid < 64) ? ks[tid] : 0.f;
        float knorm = sqrtf(blockReduceSum(kv * kv, red));

        float ip = 0.f;
        #pragma unroll 8
        for (int m = 0; m < MM; m++) ip += m0s[tid * 65 + m] * ks[m];
        float Kv = ip / (knorm * mnorm[tid] + 1e-8f);
        float x = scal[0] * Kv;
        float mx = blockReduceMax(x, red);
        float p = expf(x - mx);
        float sump = blockReduceSum(p, red);
        float wc = p / sump;

        float gg = scal[1];
        float wgv = gg * wc + (1.f - gg) * A0[(size_t)hd * BB * NN + (size_t)b * NN + tid];
        wgs[tid] = wgv;
        __syncthreads();

        float s0 = scal[2], s1 = scal[3], s2 = scal[4], gamma = scal[5];
        float conv = s0 * wgv + s1 * wgs[(tid + 255) & 255] + s2 * wgs[(tid + 1) & 255];
        float wsh = powf(conv, gamma);
        float ssum = blockReduceSum(wsh, red);
        float w = wsh / ssum;

        float* dst = hd ? wwrite : wread;
        dst[tid] = w;
        (hd ? out_ww : out_wr)[(size_t)b * NN + tid] = w;
        __syncthreads();
    }

    if (tid < 64) {
        delv[tid] = sigm(rwrow[140 + tid]);
        addv[tid] = tanhf(rwrow[204 + tid]);
    }

    {
        int q = tid >> 6, m = tid & 63;
        float s = 0.f;
        #pragma unroll 8
        for (int n = q * 64; n < q * 64 + 64; n++) s += wread[n] * m0s[n * 65 + m];
        wgs[tid] = s;
    }
    __syncthreads();
    if (tid < 64) {
        float r = wgs[tid] + wgs[64 + tid] + wgs[128 + tid] + wgs[192 + tid];
        out_Rt[(size_t)b * MM + tid] = r;
    }

    for (int e = tid; e < NN * MM; e += 256) {
        int n = e >> 6, m = e & 63;
        float ww = wwrite[n];
        float v = m0s[n * 65 + m];
        out_mt[(size_t)b * (NN * MM) + e] = v * (1.f - ww * delv[m]) + ww * addv[m];
    }
}

// ---------------- launch ----------------
extern "C" void kernel_launch(void* const* d_in, const int* in_sizes, int n_in,
                              void* d_out, int out_size)
{
    const float* x_t   = (const float*)d_in[0];
    const float* H0    = (const float*)d_in[1];
    const float* C0    = (const float*)d_in[2];
    const float* m0    = (const float*)d_in[3];
    const float* R0    = (const float*)d_in[4];
    const float* A0    = (const float*)d_in[5];
    const float* Wprep = (const float*)d_in[6];
    const float* bprep = (const float*)d_in[7];
    const float* Wx    = (const float*)d_in[8];
    const float* Wh    = (const float*)d_in[9];
    const float* bl    = (const float*)d_in[10];
    const float* Wr    = (const float*)d_in[11];
    const float* br    = (const float*)d_in[12];
    const float* Ww    = (const float*)d_in[13];
    const float* bw    = (const float*)d_in[14];
    const float* Wo    = (const float*)d_in[15];
    const float* bo    = (const float*)d_in[16];

    float* out = (float*)d_out;
    float* y  = out;
    float* mt = y + (size_t)BB * UU;
    float* Rt = mt + (size_t)BB * NN * MM;
    float* wr = Rt + (size_t)BB * MM;
    float* ww = wr + (size_t)BB * NN;

    float *hprep, *xcat, *wcat, *z, *h, *wrw, *brw, *rw, *xo;
    cudaGetSymbolAddress((void**)&hprep, g_hprep);
    cudaGetSymbolAddress((void**)&xcat, g_xcat);
    cudaGetSymbolAddress((void**)&wcat, g_wcat);
    cudaGetSymbolAddress((void**)&z, g_z);
    cudaGetSymbolAddress((void**)&h, g_h);
    cudaGetSymbolAddress((void**)&wrw, g_wrw);
    cudaGetSymbolAddress((void**)&brw, g_brw);
    cudaGetSymbolAddress((void**)&rw, g_rw);
    cudaGetSymbolAddress((void**)&xo, g_xo);

    const int T = 256;

    build_wcat<<<(KCAT * ZN + T - 1) / T, T>>>(Wx, Wh);
    build_wrw<<<(UU * RWNPAD + T - 1) / T, T>>>(Wr, Ww, br, bw);

    // h_prep = R0 @ Wprep + bprep
    {
        dim3 grid(UU / 64, BB / 64);
        sgemm<64, 64, 16, 4, 4><<<grid, 256>>>(R0, Wprep, bprep, hprep,
                                               64, 64, UU, UU, UU, 0.f);
    }

    build_xcat<<<((size_t)BB * KCAT + T - 1) / T, T>>>(x_t, H0);

    // z = Xcat @ Wcat + bl
    {
        dim3 grid(ZN / 128, BB / 128);
        sgemm<128, 128, 16, 8, 8><<<grid, 256>>>(xcat, wcat, bl, z,
                                                 KCAT, KCAT, ZN, ZN, ZN, 0.f);
    }

    gates_kernel<<<(BB * UU + T - 1) / T, T>>>(C0);

    // [r_out | w_out] = h @ [Wr | Ww] + [br | bw]
    {
        dim3 grid(RWNPAD / 64, BB / 64);
        sgemm<64, 64, 16, 4, 4><<<grid, 256>>>(h, wrw, brw, rw,
                                               UU, UU, RWNPAD, RWN, RWN, 0.f);
    }

    // addressing + memory update + R_t + w_read/w_write
    {
        size_t smem = ADDR_SMEM_FLOATS * sizeof(float);
        cudaFuncSetAttribute(ntm_addr_kernel,
                             cudaFuncAttributeMaxDynamicSharedMemorySize, (int)smem);
        ntm_addr_kernel<<<BB, 256, smem>>>(m0, A0, mt, Rt, wr, ww);
    }

    // y = [h | R_t] @ Wo + bo, clipped
    build_xo<<<((size_t)BB * XON + T - 1) / T, T>>>(Rt);
    {
        dim3 grid(UU / 64, BB / 64);
        sgemm<64, 64, 16, 4, 4><<<grid, 256>>>(xo, Wo, bo, y,
                                               XON, XON, UU, UU, UU, CLIPV);
    }
}

// round 3
// speedup vs baseline: 1.5750x; 1.5750x over previous
#include <cuda_runtime.h>
#include <math.h>
#include <stdint.h>

#define BB 2048
#define NN 256
#define MM 64
#define UU 512
#define INP 10
#define CLIPV 20.0f

#define KCAT 1056   // 10 + 512 + 512 = 1034, padded to mult of 32
#define ZN 2048
#define RWN 268     // 70 + 198
#define RWNPAD 384
#define XON 576     // 512 + 64

// ---------------- scratch (device globals, no allocation) ----------------
__device__ float g_xcat[(size_t)BB * KCAT];
__device__ float g_wcat[(size_t)KCAT * ZN];
__device__ float g_z[(size_t)BB * ZN];
__device__ float g_h[BB * UU];
__device__ float g_wrw[UU * RWNPAD];
__device__ float g_brw[RWNPAD];
__device__ float g_rw[(size_t)BB * RWN];
__device__ float g_xo[(size_t)BB * XON];

// ---------------- helpers ----------------
__device__ __forceinline__ float sigm(float x) { return 1.0f / (1.0f + expf(-x)); }
__device__ __forceinline__ float softplus(float x) {
    return (x > 20.0f) ? x : log1pf(expf(x));
}
__device__ __forceinline__ float tf32r(float x) {
    uint32_t o;
    asm("cvt.rna.tf32.f32 %0, %1;" : "=r"(o) : "f"(x));
    return __uint_as_float(o);
}
__device__ __forceinline__ void mma_tf32(float* d, const uint32_t* a,
                                         const uint32_t* b, const float* c) {
    asm volatile(
        "mma.sync.aligned.m16n8k8.row.col.f32.tf32.tf32.f32 "
        "{%0,%1,%2,%3}, {%4,%5,%6,%7}, {%8,%9}, {%10,%11,%12,%13};\n"
        : "=f"(d[0]), "=f"(d[1]), "=f"(d[2]), "=f"(d[3])
        : "r"(a[0]), "r"(a[1]), "r"(a[2]), "r"(a[3]),
          "r"(b[0]), "r"(b[1]),
          "f"(c[0]), "f"(c[1]), "f"(c[2]), "f"(c[3]));
}

__device__ __forceinline__ float blockReduceSum(float v, volatile float* red) {
    #pragma unroll
    for (int o = 16; o; o >>= 1) v += __shfl_xor_sync(0xffffffffu, v, o);
    if ((threadIdx.x & 31) == 0) red[threadIdx.x >> 5] = v;
    __syncthreads();
    if (threadIdx.x == 0) {
        float s = 0.f;
        #pragma unroll
        for (int i = 0; i < 8; i++) s += red[i];
        red[0] = s;
    }
    __syncthreads();
    float r = red[0];
    __syncthreads();
    return r;
}

__device__ __forceinline__ float blockReduceMax(float v, volatile float* red) {
    #pragma unroll
    for (int o = 16; o; o >>= 1) v = fmaxf(v, __shfl_xor_sync(0xffffffffu, v, o));
    if ((threadIdx.x & 31) == 0) red[threadIdx.x >> 5] = v;
    __syncthreads();
    if (threadIdx.x == 0) {
        float s = red[0];
        #pragma unroll
        for (int i = 1; i < 8; i++) s = fmaxf(s, red[i]);
        red[0] = s;
    }
    __syncthreads();
    float r = red[0];
    __syncthreads();
    return r;
}

// ---------------- tf32 tensor-core GEMM: C = clip(A(MxK) @ B(KxN) + bias) ----
// BM=128, BN=128, BK=32. 256 threads = 8 warps (2x4), warp tile 64x32,
// 4x4 m16n8k8 mma tiles per warp. K must be a multiple of 32; M mult of 128;
// padded B buffers guarantee full-tile loads; only stores guarded by Nreal.
__global__ __launch_bounds__(256, 2)
void mma_gemm(const float* __restrict__ A, const float* __restrict__ Bm,
              const float* __restrict__ bias, float* __restrict__ C,
              int Kdim, int lda, int ldb, int ldc, int Nreal, float clipv)
{
    __shared__ float As[128][40];   // row-major [m][k], stride 40 (16B-aligned rows)
    __shared__ float Bs[32][136];   // [k][n], stride 136 -> conflict-free frag loads

    const int tid = threadIdx.x;
    const int lane = tid & 31;
    const int warp = tid >> 5;
    const int wm = warp >> 2;       // 0..1
    const int wn = warp & 3;        // 0..3
    const int brow = blockIdx.y * 128;
    const int bcol = blockIdx.x * 128;
    const int lq = lane >> 2;       // 0..7
    const int lr = lane & 3;        // 0..3

    float acc[4][4][4];
    #pragma unroll
    for (int i = 0; i < 4; i++)
        #pragma unroll
        for (int j = 0; j < 4; j++)
            #pragma unroll
            for (int t = 0; t < 4; t++) acc[i][j][t] = 0.f;

    for (int k0 = 0; k0 < Kdim; k0 += 32) {
        // A tile: 128x32 floats, float4 per thread x4
        #pragma unroll
        for (int l = 0; l < 4; l++) {
            int idx = (tid + l * 256) * 4;
            int r = idx >> 5, c = idx & 31;
            float4 v = *(const float4*)(A + (size_t)(brow + r) * lda + k0 + c);
            As[r][c + 0] = tf32r(v.x);
            As[r][c + 1] = tf32r(v.y);
            As[r][c + 2] = tf32r(v.z);
            As[r][c + 3] = tf32r(v.w);
        }
        // B tile: 32x128 floats
        #pragma unroll
        for (int l = 0; l < 4; l++) {
            int idx = (tid + l * 256) * 4;
            int r = idx >> 7, c = idx & 127;
            float4 v = *(const float4*)(Bm + (size_t)(k0 + r) * ldb + bcol + c);
            Bs[r][c + 0] = tf32r(v.x);
            Bs[r][c + 1] = tf32r(v.y);
            Bs[r][c + 2] = tf32r(v.z);
            Bs[r][c + 3] = tf32r(v.w);
        }
        __syncthreads();

        #pragma unroll
        for (int kk = 0; kk < 4; kk++) {
            const int kb = kk * 8;
            uint32_t af[4][4], bf[4][2];
            #pragma unroll
            for (int mt = 0; mt < 4; mt++) {
                int m = wm * 64 + mt * 16 + lq;
                int k = kb + lr;
                af[mt][0] = __float_as_uint(As[m][k]);
                af[mt][1] = __float_as_uint(As[m + 8][k]);
                af[mt][2] = __float_as_uint(As[m][k + 4]);
                af[mt][3] = __float_as_uint(As[m + 8][k + 4]);
            }
            #pragma unroll
            for (int nt = 0; nt < 4; nt++) {
                int n = wn * 32 + nt * 8 + lq;
                int k = kb + lr;
                bf[nt][0] = __float_as_uint(Bs[k][n]);
                bf[nt][1] = __float_as_uint(Bs[k + 4][n]);
            }
            #pragma unroll
            for (int mt = 0; mt < 4; mt++)
                #pragma unroll
                for (int nt = 0; nt < 4; nt++)
                    mma_tf32(acc[mt][nt], af[mt], bf[nt], acc[mt][nt]);
        }
        __syncthreads();
    }

    // epilogue: bias + optional clip, float2 stores
    #pragma unroll
    for (int mt = 0; mt < 4; mt++) {
        #pragma unroll
        for (int half = 0; half < 2; half++) {
            int row = brow + wm * 64 + mt * 16 + lq + half * 8;
            #pragma unroll
            for (int nt = 0; nt < 4; nt++) {
                int col = bcol + wn * 32 + nt * 8 + lr * 2;
                if (col < Nreal) {
                    float v0 = acc[mt][nt][half * 2 + 0] + bias[col];
                    float v1 = acc[mt][nt][half * 2 + 1] + bias[col + 1];
                    if (clipv > 0.f) {
                        v0 = fminf(fmaxf(v0, -clipv), clipv);
                        v1 = fminf(fmaxf(v1, -clipv), clipv);
                    }
                    *(float2*)(C + (size_t)row * ldc + col) = make_float2(v0, v1);
                }
            }
        }
    }
}

// ---------------- build / pointwise kernels ----------------
__global__ void build_wcat(const float* __restrict__ Wx, const float* __restrict__ Wh) {
    int idx = blockIdx.x * 256 + threadIdx.x;
    if (idx >= KCAT * ZN) return;
    int r = idx / ZN, c = idx % ZN;
    float v = 0.f;
    if (r < 522) v = Wx[r * ZN + c];
    else if (r < 1034) v = Wh[(r - 522) * ZN + c];
    g_wcat[idx] = v;
}

// fills x_t part, H0 part and zero padding; cols [10,522) are overwritten
// later by the hprep GEMM (stream-ordered), so whatever we write there is dead.
__global__ void build_xcat(const float* __restrict__ x_t, const float* __restrict__ H0) {
    int idx = blockIdx.x * 256 + threadIdx.x;
    if (idx >= BB * KCAT) return;
    int b = idx / KCAT, c = idx % KCAT;
    float v = 0.f;
    if (c < INP) v = x_t[b * INP + c];
    else if (c < 522) v = 0.f;                      // hprep GEMM writes here
    else if (c < 1034) v = H0[b * UU + (c - 522)];
    g_xcat[idx] = v;
}

__global__ void build_wrw(const float* __restrict__ Wr, const float* __restrict__ Ww,
                          const float* __restrict__ br, const float* __restrict__ bw) {
    int idx = blockIdx.x * 256 + threadIdx.x;
    if (idx < RWNPAD) {
        float bv = 0.f;
        if (idx < 70) bv = br[idx];
        else if (idx < RWN) bv = bw[idx - 70];
        g_brw[idx] = bv;
    }
    if (idx >= UU * RWNPAD) return;
    int r = idx / RWNPAD, c = idx % RWNPAD;
    float v = 0.f;
    if (c < 70) v = Wr[r * 70 + c];
    else if (c < RWN) v = Ww[r * 198 + (c - 70)];
    g_wrw[idx] = v;
}

__global__ void gates_kernel(const float* __restrict__ C0) {
    int idx = blockIdx.x * 256 + threadIdx.x;
    if (idx >= BB * UU) return;
    int b = idx / UU, u = idx % UU;
    const float* zr = g_z + (size_t)b * ZN;
    float gi = zr[u], gf = zr[u + 512], gg = zr[u + 1024], go = zr[u + 1536];
    float c = sigm(gf) * C0[idx] + sigm(gi) * tanhf(gg);
    float h = sigm(go) * tanhf(c);
    h = fminf(fmaxf(h, -CLIPV), CLIPV);
    g_h[idx] = h;
}

__global__ void build_xo(const float* __restrict__ Rt) {
    int idx = blockIdx.x * 256 + threadIdx.x;
    if (idx >= BB * XON) return;
    int b = idx / XON, c = idx % XON;
    g_xo[idx] = (c < UU) ? g_h[b * UU + c] : Rt[b * MM + (c - UU)];
}

// ---------------- NTM addressing + memory update (one CTA per batch row) ----
#define ADDR_SMEM_FLOATS (16640 + 256 + 64 + 256 + 256 + 256 + 64 + 64 + 32 + 8)

__global__ __launch_bounds__(256)
void ntm_addr_kernel(const float* __restrict__ m0, const float* __restrict__ A0,
                     float* __restrict__ out_mt, float* __restrict__ out_Rt,
                     float* __restrict__ out_wr, float* __restrict__ out_ww)
{
    extern __shared__ float sm[];
    float* m0s    = sm;
    float* mnorm  = sm + 16640;
    float* ks     = mnorm + 256;
    float* wgs    = ks + 64;
    float* wread  = wgs + 256;
    float* wwrite = wread + 256;
    float* delv   = wwrite + 256;
    float* addv   = delv + 64;
    float* red    = addv + 64;
    float* scal   = red + 32;

    const int b = blockIdx.x;
    const int tid = threadIdx.x;
    const float* m0g = m0 + (size_t)b * (NN * MM);

    for (int e = tid; e < NN * MM; e += 256)
        m0s[(e >> 6) * 65 + (e & 63)] = m0g[e];
    __syncthreads();

    {
        float s = 0.f;
        #pragma unroll 8
        for (int m = 0; m < MM; m++) { float v = m0s[tid * 65 + m]; s += v * v; }
        mnorm[tid] = sqrtf(s);
    }

    const float* rwrow = g_rw + (size_t)b * RWN;

    for (int hd = 0; hd < 2; hd++) {
        const float* head = rwrow + (hd ? 70 : 0);
        if (tid < 64) ks[tid] = tanhf(head[tid]);
        if (tid == 64) {
            scal[0] = softplus(head[64]);
            scal[1] = sigm(head[65]);
            float a = head[66], bq = head[67], cq = head[68];
            float mx = fmaxf(a, fmaxf(bq, cq));
            float e0 = expf(a - mx), e1 = expf(bq - mx), e2 = expf(cq - mx);
            float se = e0 + e1 + e2;
            scal[2] = e0 / se; scal[3] = e1 / se; scal[4] = e2 / se;
            scal[5] = softplus(head[69]);
        }
        __syncthreads();

        float kv = (tid < 64) ? ks[tid] : 0.f;
        float knorm = sqrtf(blockReduceSum(kv * kv, red));

        float ip = 0.f;
        #pragma unroll 8
        for (int m = 0; m < MM; m++) ip += m0s[tid * 65 + m] * ks[m];
        float Kv = ip / (knorm * mnorm[tid] + 1e-8f);
        float x = scal[0] * Kv;
        float mx = blockReduceMax(x, red);
        float p = expf(x - mx);
        float sump = blockReduceSum(p, red);
        float wc = p / sump;

        float gg = scal[1];
        float wgv = gg * wc + (1.f - gg) * A0[(size_t)hd * BB * NN + (size_t)b * NN + tid];
        wgs[tid] = wgv;
        __syncthreads();

        float s0 = scal[2], s1 = scal[3], s2 = scal[4], gamma = scal[5];
        float conv = s0 * wgv + s1 * wgs[(tid + 255) & 255] + s2 * wgs[(tid + 1) & 255];
        float wsh = powf(conv, gamma);
        float ssum = blockReduceSum(wsh, red);
        float w = wsh / ssum;

        float* dst = hd ? wwrite : wread;
        dst[tid] = w;
        (hd ? out_ww : out_wr)[(size_t)b * NN + tid] = w;
        __syncthreads();
    }

    if (tid < 64) {
        delv[tid] = sigm(rwrow[140 + tid]);
        addv[tid] = tanhf(rwrow[204 + tid]);
    }

    {
        int q = tid >> 6, m = tid & 63;
        float s = 0.f;
        #pragma unroll 8
        for (int n = q * 64; n < q * 64 + 64; n++) s += wread[n] * m0s[n * 65 + m];
        wgs[tid] = s;
    }
    __syncthreads();
    if (tid < 64) {
        float r = wgs[tid] + wgs[64 + tid] + wgs[128 + tid] + wgs[192 + tid];
        out_Rt[(size_t)b * MM + tid] = r;
    }

    for (int e = tid; e < NN * MM; e += 256) {
        int n = e >> 6, m = e & 63;
        float ww = wwrite[n];
        float v = m0s[n * 65 + m];
        out_mt[(size_t)b * (NN * MM) + e] = v * (1.f - ww * delv[m]) + ww * addv[m];
    }
}

// ---------------- launch ----------------
extern "C" void kernel_launch(void* const* d_in, const int* in_sizes, int n_in,
                              void* d_out, int out_size)
{
    const float* x_t   = (const float*)d_in[0];
    const float* H0    = (const float*)d_in[1];
    const float* C0    = (const float*)d_in[2];
    const float* m0    = (const float*)d_in[3];
    const float* R0    = (const float*)d_in[4];
    const float* A0    = (const float*)d_in[5];
    const float* Wprep = (const float*)d_in[6];
    const float* bprep = (const float*)d_in[7];
    const float* Wx    = (const float*)d_in[8];
    const float* Wh    = (const float*)d_in[9];
    const float* bl    = (const float*)d_in[10];
    const float* Wr    = (const float*)d_in[11];
    const float* br    = (const float*)d_in[12];
    const float* Ww    = (const float*)d_in[13];
    const float* bw    = (const float*)d_in[14];
    const float* Wo    = (const float*)d_in[15];
    const float* bo    = (const float*)d_in[16];

    float* out = (float*)d_out;
    float* y  = out;
    float* mt = y + (size_t)BB * UU;
    float* Rt = mt + (size_t)BB * NN * MM;
    float* wr = Rt + (size_t)BB * MM;
    float* ww = wr + (size_t)BB * NN;

    float *xcat, *wcat, *z, *h, *wrw, *brw, *rw, *xo;
    cudaGetSymbolAddress((void**)&xcat, g_xcat);
    cudaGetSymbolAddress((void**)&wcat, g_wcat);
    cudaGetSymbolAddress((void**)&z, g_z);
    cudaGetSymbolAddress((void**)&h, g_h);
    cudaGetSymbolAddress((void**)&wrw, g_wrw);
    cudaGetSymbolAddress((void**)&brw, g_brw);
    cudaGetSymbolAddress((void**)&rw, g_rw);
    cudaGetSymbolAddress((void**)&xo, g_xo);

    const int T = 256;

    build_wcat<<<(KCAT * ZN + T - 1) / T, T>>>(Wx, Wh);
    build_wrw<<<(UU * RWNPAD + T - 1) / T, T>>>(Wr, Ww, br, bw);
    build_xcat<<<(int)(((size_t)BB * KCAT + T - 1) / T), T>>>(x_t, H0);

    // h_prep = R0 @ Wprep + bprep  -> written straight into xcat cols [10,522)
    {
        dim3 grid(UU / 128, BB / 128);
        mma_gemm<<<grid, 256>>>(R0, Wprep, bprep, xcat + INP,
                                64, 64, UU, KCAT, UU, 0.f);
    }

    // z = Xcat @ Wcat + bl
    {
        dim3 grid(ZN / 128, BB / 128);
        mma_gemm<<<grid, 256>>>(xcat, wcat, bl, z,
                                KCAT, KCAT, ZN, ZN, ZN, 0.f);
    }

    gates_kernel<<<(BB * UU + T - 1) / T, T>>>(C0);

    // [r_out | w_out] = h @ [Wr | Ww] + [br | bw]
    {
        dim3 grid(RWNPAD / 128, BB / 128);
        mma_gemm<<<grid, 256>>>(h, wrw, brw, rw,
                                UU, UU, RWNPAD, RWN, RWN, 0.f);
    }

    // addressing + memory update + R_t + w_read/w_write
    {
        size_t smem = ADDR_SMEM_FLOATS * sizeof(float);
        cudaFuncSetAttribute(ntm_addr_kernel,
                             cudaFuncAttributeMaxDynamicSharedMemorySize, (int)smem);
        ntm_addr_kernel<<<BB, 256, smem>>>(m0, A0, mt, Rt, wr, ww);
    }

    // y = [h | R_t] @ Wo + bo, clipped
    build_xo<<<(int)(((size_t)BB * XON + T - 1) / T), T>>>(Rt);
    {
        dim3 grid(UU / 128, BB / 128);
        mma_gemm<<<grid, 256>>>(xo, Wo, bo, y,
                                XON, XON, UU, UU, UU, CLIPV);
    }
}

// round 5
// speedup vs baseline: 2.4885x; 1.5800x over previous
#include <cuda_runtime.h>
#include <cuda_fp16.h>
#include <math.h>
#include <stdint.h>

#define BB 2048
#define NN 256
#define MM 64
#define UU 512
#define INP 10
#define CLIPV 20.0f

#define KCAT 1056   // 10 + 512 + 512 = 1034, padded to mult of 32
#define ZN 2048
#define RWN 268     // 70 + 198
#define RWNPAD 384
#define XON 576     // 512 + 64

// ---------------- scratch (device globals, no allocation) ----------------
__device__ __align__(256) __half g_xcat[(size_t)BB * KCAT];   // A for z GEMM (half)
__device__ __align__(256) __half g_wcat_t[(size_t)ZN * KCAT]; // Bt [n][k] half
__device__ __align__(256) float  g_z[(size_t)BB * ZN];
__device__ __align__(256) __half g_h[BB * UU];
__device__ __align__(256) __half g_wrw_t[(size_t)RWNPAD * UU];
__device__ __align__(256) float  g_brw[RWNPAD];
__device__ __align__(256) float  g_rw[(size_t)BB * RWN];
__device__ __align__(256) __half g_xo[(size_t)BB * XON];
__device__ __align__(256) __half g_wo_t[(size_t)UU * XON];
__device__ __align__(256) __half g_wprep_t[(size_t)UU * MM];
__device__ __align__(256) __half g_r0h[(size_t)BB * MM];

// ---------------- helpers ----------------
__device__ __forceinline__ float sigm(float x) { return 1.0f / (1.0f + expf(-x)); }
__device__ __forceinline__ float softplus(float x) {
    return (x > 20.0f) ? x : log1pf(expf(x));
}

__device__ __forceinline__ void cpasync16(const void* smem_dst, const void* gsrc) {
    uint32_t d = (uint32_t)__cvta_generic_to_shared(smem_dst);
    asm volatile("cp.async.cg.shared.global [%0], [%1], 16;\n" :: "r"(d), "l"(gsrc));
}
__device__ __forceinline__ void cpasync_commit() {
    asm volatile("cp.async.commit_group;\n");
}
template<int NW> __device__ __forceinline__ void cpasync_wait() {
    asm volatile("cp.async.wait_group %0;\n" :: "n"(NW));
}
__device__ __forceinline__ void ldsm4(uint32_t& r0, uint32_t& r1, uint32_t& r2,
                                      uint32_t& r3, const __half* p) {
    uint32_t a = (uint32_t)__cvta_generic_to_shared(p);
    asm volatile("ldmatrix.sync.aligned.m8n8.x4.shared.b16 {%0,%1,%2,%3}, [%4];\n"
        : "=r"(r0), "=r"(r1), "=r"(r2), "=r"(r3) : "r"(a));
}
__device__ __forceinline__ void mma16816(float* d, const uint32_t* a,
                                         uint32_t b0, uint32_t b1) {
    asm volatile(
        "mma.sync.aligned.m16n8k16.row.col.f32.f16.f16.f32 "
        "{%0,%1,%2,%3}, {%4,%5,%6,%7}, {%8,%9}, {%0,%1,%2,%3};\n"
        : "+f"(d[0]), "+f"(d[1]), "+f"(d[2]), "+f"(d[3])
        : "r"(a[0]), "r"(a[1]), "r"(a[2]), "r"(a[3]), "r"(b0), "r"(b1));
}

__device__ __forceinline__ float blockReduceSum(float v, volatile float* red) {
    #pragma unroll
    for (int o = 16; o; o >>= 1) v += __shfl_xor_sync(0xffffffffu, v, o);
    if ((threadIdx.x & 31) == 0) red[threadIdx.x >> 5] = v;
    __syncthreads();
    if (threadIdx.x == 0) {
        float s = 0.f;
        #pragma unroll
        for (int i = 0; i < 8; i++) s += red[i];
        red[0] = s;
    }
    __syncthreads();
    float r = red[0];
    __syncthreads();
    return r;
}
__device__ __forceinline__ float blockReduceMax(float v, volatile float* red) {
    #pragma unroll
    for (int o = 16; o; o >>= 1) v = fmaxf(v, __shfl_xor_sync(0xffffffffu, v, o));
    if ((threadIdx.x & 31) == 0) red[threadIdx.x >> 5] = v;
    __syncthreads();
    if (threadIdx.x == 0) {
        float s = red[0];
        #pragma unroll
        for (int i = 1; i < 8; i++) s = fmaxf(s, red[i]);
        red[0] = s;
    }
    __syncthreads();
    float r = red[0];
    __syncthreads();
    return r;
}

// ---------------- fp16 tensor-core GEMM ----------------
// C[M,N] = clip(A[M,K](half,row-major) @ Bt[N,K]^T (half, n-major) + bias)
// BK=32. Warp tile = (MT*16) x (NT*8). 2-stage cp.async pipeline, ldmatrix frags.
// K mult of 32, M mult of BM, N(padded rows of Bt) mult of BN; stores guarded by Nreal.
template<int BM, int BN, int WM, int WN, int MT, int NT, typename OutT>
__global__ __launch_bounds__(WM * WN * 32, 2)
void hgemm(const __half* __restrict__ A, const __half* __restrict__ Bt,
           const float* __restrict__ bias, OutT* __restrict__ C,
           int Kdim, int lda, int ldb, int ldc, int Nreal, float clipv)
{
    constexpr int THREADS = WM * WN * 32;
    __shared__ __half As[2][BM * 40];
    __shared__ __half Bs[2][BN * 40];

    const int tid  = threadIdx.x;
    const int lane = tid & 31;
    const int warp = tid >> 5;
    const int wm = warp / WN;
    const int wn = warp % WN;
    const int brow = blockIdx.y * BM;
    const int bcol = blockIdx.x * BN;
    const int lq = lane >> 2;
    const int lr = lane & 3;

    const __half* Ablk = A + (size_t)brow * lda;
    const __half* Bblk = Bt + (size_t)bcol * ldb;

    float acc[MT][NT][4];
    #pragma unroll
    for (int i = 0; i < MT; i++)
        #pragma unroll
        for (int j = 0; j < NT; j++)
            #pragma unroll
            for (int t = 0; t < 4; t++) acc[i][j][t] = 0.f;

    // ldmatrix source addresses (per-lane)
    const int a_row = (lane & 7) + ((lane >> 3) & 1) * 8;
    const int a_ch  = (lane >> 4) * 8;
    const int b_row = ((lane >> 4) & 1) * 8 + (lane & 7);
    const int b_ch  = ((lane >> 3) & 1) * 8;

    const int KT = Kdim / 32;

    auto loadTile = [&](int buf, int k0) {
        #pragma unroll
        for (int i = 0; i < (BM * 4) / THREADS; i++) {
            int ch = tid + i * THREADS;
            int r = ch >> 2, co = (ch & 3) * 8;
            cpasync16(&As[buf][r * 40 + co], Ablk + (size_t)r * lda + k0 + co);
        }
        #pragma unroll
        for (int i = 0; i < (BN * 4) / THREADS; i++) {
            int ch = tid + i * THREADS;
            int r = ch >> 2, co = (ch & 3) * 8;
            cpasync16(&Bs[buf][r * 40 + co], Bblk + (size_t)r * ldb + k0 + co);
        }
        cpasync_commit();
    };

    auto computeTile = [&](int buf) {
        const __half* as = As[buf];
        const __half* bs = Bs[buf];
        #pragma unroll
        for (int kk = 0; kk < 2; kk++) {
            uint32_t af[MT][4];
            #pragma unroll
            for (int mt = 0; mt < MT; mt++) {
                int row = wm * (MT * 16) + mt * 16 + a_row;
                ldsm4(af[mt][0], af[mt][1], af[mt][2], af[mt][3],
                      as + row * 40 + kk * 16 + a_ch);
            }
            uint32_t bf[NT][2];
            #pragma unroll
            for (int p = 0; p < NT / 2; p++) {
                int row = wn * (NT * 8) + p * 16 + b_row;
                ldsm4(bf[2 * p][0], bf[2 * p][1], bf[2 * p + 1][0], bf[2 * p + 1][1],
                      bs + row * 40 + kk * 16 + b_ch);
            }
            #pragma unroll
            for (int mt = 0; mt < MT; mt++)
                #pragma unroll
                for (int nt = 0; nt < NT; nt++)
                    mma16816(acc[mt][nt], af[mt], bf[nt][0], bf[nt][1]);
        }
    };

    loadTile(0, 0);
    for (int kt = 0; kt < KT - 1; kt++) {
        loadTile((kt + 1) & 1, (kt + 1) * 32);
        cpasync_wait<1>();
        __syncthreads();
        computeTile(kt & 1);
        __syncthreads();
    }
    cpasync_wait<0>();
    __syncthreads();
    computeTile((KT - 1) & 1);

    // epilogue
    #pragma unroll
    for (int mt = 0; mt < MT; mt++) {
        #pragma unroll
        for (int hh = 0; hh < 2; hh++) {
            int row = brow + wm * (MT * 16) + mt * 16 + lq + hh * 8;
            #pragma unroll
            for (int nt = 0; nt < NT; nt++) {
                int col = bcol + wn * (NT * 8) + nt * 8 + lr * 2;
                if (col < Nreal) {
                    float v0 = acc[mt][nt][hh * 2 + 0] + bias[col];
                    float v1 = acc[mt][nt][hh * 2 + 1] + bias[col + 1];
                    if (clipv > 0.f) {
                        v0 = fminf(fmaxf(v0, -clipv), clipv);
                        v1 = fminf(fmaxf(v1, -clipv), clipv);
                    }
                    if (sizeof(OutT) == 2) {
                        *(__half2*)((__half*)C + (size_t)row * ldc + col) =
                            __halves2half2(__float2half_rn(v0), __float2half_rn(v1));
                    } else {
                        *(float2*)((float*)C + (size_t)row * ldc + col) =
                            make_float2(v0, v1);
                    }
                }
            }
        }
    }
}

// ---------------- transpose fp32 [R][C] -> half [C][ldDst] at col kOff ------
__global__ void transpose_f2h(const float* __restrict__ src, __half* __restrict__ dst,
                              int R, int Rlim, int C, int ldDst, int kOff)
{
    __shared__ float t[32][33];
    int cb = blockIdx.x * 32, rb = blockIdx.y * 32;
    int x = threadIdx.x, y = threadIdx.y;
    #pragma unroll
    for (int i = 0; i < 32; i += 8) {
        int r = rb + y + i, c = cb + x;
        t[y + i][x] = (r < R && c < C) ? src[(size_t)r * C + c] : 0.f;
    }
    __syncthreads();
    #pragma unroll
    for (int i = 0; i < 32; i += 8) {
        int c = cb + y + i, r = rb + x;
        if (c < C && r < Rlim)
            dst[(size_t)c * ldDst + kOff + r] = __float2half(t[x][y + i]);
    }
}

__global__ void zfill_half(__half* dst, int count) {
    int i = blockIdx.x * 256 + threadIdx.x;
    if (i < count) dst[i] = __ushort_as_half(0);
}
__global__ void zpad_cols(__half* dst, int ld, int start, int len, int rows) {
    int i = blockIdx.x * 256 + threadIdx.x;
    if (i >= rows * len) return;
    dst[(size_t)(i / len) * ld + start + (i % len)] = __ushort_as_half(0);
}

// ---------------- build / pointwise kernels ----------------
__global__ void build_xcat(const float* __restrict__ x_t, const float* __restrict__ H0) {
    int idx = blockIdx.x * 256 + threadIdx.x;
    if (idx >= BB * KCAT) return;
    int b = idx / KCAT, c = idx % KCAT;
    float v = 0.f;
    if (c < INP) v = x_t[b * INP + c];
    else if (c >= 522 && c < 1034) v = H0[b * UU + (c - 522)];
    g_xcat[idx] = __float2half(v);   // cols [10,522) overwritten by hprep GEMM
}

__global__ void prep_misc(const float* __restrict__ R0, const float* __restrict__ br,
                          const float* __restrict__ bw) {
    int idx = blockIdx.x * 256 + threadIdx.x;
    if (idx < RWNPAD) {
        float bv = 0.f;
        if (idx < 70) bv = br[idx];
        else if (idx < RWN) bv = bw[idx - 70];
        g_brw[idx] = bv;
    }
    if (idx < BB * MM) g_r0h[idx] = __float2half(R0[idx]);
}

__global__ void gates_kernel(const float* __restrict__ C0) {
    int idx = blockIdx.x * 256 + threadIdx.x;
    if (idx >= BB * UU) return;
    int b = idx / UU, u = idx % UU;
    const float* zr = g_z + (size_t)b * ZN;
    float gi = zr[u], gf = zr[u + 512], gg = zr[u + 1024], go = zr[u + 1536];
    float c = sigm(gf) * C0[idx] + sigm(gi) * tanhf(gg);
    float h = sigm(go) * tanhf(c);
    h = fminf(fmaxf(h, -CLIPV), CLIPV);
    g_h[idx] = __float2half(h);
}

__global__ void build_xo(const float* __restrict__ Rt) {
    int idx = blockIdx.x * 256 + threadIdx.x;
    if (idx >= BB * XON) return;
    int b = idx / XON, c = idx % XON;
    g_xo[idx] = (c < UU) ? g_h[b * UU + c] : __float2half(Rt[b * MM + (c - UU)]);
}

// ---------------- NTM addressing + memory update (one CTA per batch row) ----
#define ADDR_SMEM_FLOATS (16640 + 256 + 64 + 256 + 256 + 256 + 64 + 64 + 32 + 8)

__global__ __launch_bounds__(256)
void ntm_addr_kernel(const float* __restrict__ m0, const float* __restrict__ A0,
                     float* __restrict__ out_mt, float* __restrict__ out_Rt,
                     float* __restrict__ out_wr, float* __restrict__ out_ww)
{
    extern __shared__ float sm[];
    float* m0s    = sm;
    float* mnorm  = sm + 16640;
    float* ks     = mnorm + 256;
    float* wgs    = ks + 64;
    float* wread  = wgs + 256;
    float* wwrite = wread + 256;
    float* delv   = wwrite + 256;
    float* addv   = delv + 64;
    float* red    = addv + 64;
    float* scal   = red + 32;

    const int b = blockIdx.x;
    const int tid = threadIdx.x;
    const float4* m0g4 = (const float4*)(m0 + (size_t)b * (NN * MM));

    #pragma unroll 4
    for (int e4 = tid; e4 < NN * MM / 4; e4 += 256) {
        float4 v = m0g4[e4];
        int n = e4 >> 4, m = (e4 & 15) * 4;
        float* p = &m0s[n * 65 + m];
        p[0] = v.x; p[1] = v.y; p[2] = v.z; p[3] = v.w;
    }
    __syncthreads();

    {
        float s = 0.f;
        #pragma unroll 8
        for (int m = 0; m < MM; m++) { float v = m0s[tid * 65 + m]; s += v * v; }
        mnorm[tid] = sqrtf(s);
    }

    const float* rwrow = g_rw + (size_t)b * RWN;

    for (int hd = 0; hd < 2; hd++) {
        const float* head = rwrow + (hd ? 70 : 0);
        if (tid < 64) ks[tid] = tanhf(head[tid]);
        if (tid == 64) {
            scal[0] = softplus(head[64]);
            scal[1] = sigm(head[65]);
            float a = head[66], bq = head[67], cq = head[68];
            float mx = fmaxf(a, fmaxf(bq, cq));
            float e0 = expf(a - mx), e1 = expf(bq - mx), e2 = expf(cq - mx);
            float se = e0 + e1 + e2;
            scal[2] = e0 / se; scal[3] = e1 / se; scal[4] = e2 / se;
            scal[5] = softplus(head[69]);
        }
        __syncthreads();

        float kv = (tid < 64) ? ks[tid] : 0.f;
        float knorm = sqrtf(blockReduceSum(kv * kv, red));

        float ip = 0.f;
        #pragma unroll 8
        for (int m = 0; m < MM; m++) ip += m0s[tid * 65 + m] * ks[m];
        float Kv = ip / (knorm * mnorm[tid] + 1e-8f);
        float x = scal[0] * Kv;
        float mx = blockReduceMax(x, red);
        float p = expf(x - mx);
        float sump = blockReduceSum(p, red);
        float wc = p / sump;

        float gg = scal[1];
        float wgv = gg * wc + (1.f - gg) * A0[(size_t)hd * BB * NN + (size_t)b * NN + tid];
        wgs[tid] = wgv;
        __syncthreads();

        float s0 = scal[2], s1 = scal[3], s2 = scal[4], gamma = scal[5];
        float conv = s0 * wgv + s1 * wgs[(tid + 255) & 255] + s2 * wgs[(tid + 1) & 255];
        float wsh = powf(conv, gamma);
        float ssum = blockReduceSum(wsh, red);
        float w = wsh / ssum;

        float* dst = hd ? wwrite : wread;
        dst[tid] = w;
        (hd ? out_ww : out_wr)[(size_t)b * NN + tid] = w;
        __syncthreads();
    }

    if (tid < 64) {
        delv[tid] = sigm(rwrow[140 + tid]);
        addv[tid] = tanhf(rwrow[204 + tid]);
    }

    {
        int q = tid >> 6, m = tid & 63;
        float s = 0.f;
        #pragma unroll 8
        for (int n = q * 64; n < q * 64 + 64; n++) s += wread[n] * m0s[n * 65 + m];
        wgs[tid] = s;
    }
    __syncthreads();
    if (tid < 64) {
        float r = wgs[tid] + wgs[64 + tid] + wgs[128 + tid] + wgs[192 + tid];
        out_Rt[(size_t)b * MM + tid] = r;
    }

    float4* mt4 = (float4*)(out_mt + (size_t)b * (NN * MM));
    #pragma unroll 4
    for (int e4 = tid; e4 < NN * MM / 4; e4 += 256) {
        int n = e4 >> 4, m = (e4 & 15) * 4;
        float ww = wwrite[n];
        const float* p = &m0s[n * 65 + m];
        float4 v;
        v.x = p[0] * (1.f - ww * delv[m + 0]) + ww * addv[m + 0];
        v.y = p[1] * (1.f - ww * delv[m + 1]) + ww * addv[m + 1];
        v.z = p[2] * (1.f - ww * delv[m + 2]) + ww * addv[m + 2];
        v.w = p[3] * (1.f - ww * delv[m + 3]) + ww * addv[m + 3];
        mt4[e4] = v;
    }
}

// ---------------- launch ----------------
extern "C" void kernel_launch(void* const* d_in, const int* in_sizes, int n_in,
                              void* d_out, int out_size)
{
    const float* x_t   = (const float*)d_in[0];
    const float* H0    = (const float*)d_in[1];
    const float* C0    = (const float*)d_in[2];
    const float* m0    = (const float*)d_in[3];
    const float* R0    = (const float*)d_in[4];
    const float* A0    = (const float*)d_in[5];
    const float* Wprep = (const float*)d_in[6];
    const float* bprep = (const float*)d_in[7];
    const float* Wx    = (const float*)d_in[8];
    const float* Wh    = (const float*)d_in[9];
    const float* bl    = (const float*)d_in[10];
    const float* Wr    = (const float*)d_in[11];
    const float* br    = (const float*)d_in[12];
    const float* Ww    = (const float*)d_in[13];
    const float* bw    = (const float*)d_in[14];
    const float* Wo    = (const float*)d_in[15];
    const float* bo    = (const float*)d_in[16];

    float* out = (float*)d_out;
    float* y  = out;
    float* mt = y + (size_t)BB * UU;
    float* Rt = mt + (size_t)BB * NN * MM;
    float* wr = Rt + (size_t)BB * MM;
    float* ww = wr + (size_t)BB * NN;

    __half *xcat, *wcat_t, *h, *wrw_t, *xo, *wo_t, *wprep_t, *r0h;
    float *z, *brw, *rw;
    cudaGetSymbolAddress((void**)&xcat, g_xcat);
    cudaGetSymbolAddress((void**)&wcat_t, g_wcat_t);
    cudaGetSymbolAddress((void**)&z, g_z);
    cudaGetSymbolAddress((void**)&h, g_h);
    cudaGetSymbolAddress((void**)&wrw_t, g_wrw_t);
    cudaGetSymbolAddress((void**)&brw, g_brw);
    cudaGetSymbolAddress((void**)&rw, g_rw);
    cudaGetSymbolAddress((void**)&xo, g_xo);
    cudaGetSymbolAddress((void**)&wo_t, g_wo_t);
    cudaGetSymbolAddress((void**)&wprep_t, g_wprep_t);
    cudaGetSymbolAddress((void**)&r0h, g_r0h);

    const int T = 256;
    dim3 tb(32, 8);

    // ---- weight preprocessing (half, transposed [n][k]) ----
    transpose_f2h<<<dim3(64, 17), tb>>>(Wx, wcat_t, 522, 522, ZN, KCAT, 0);
    transpose_f2h<<<dim3(64, 16), tb>>>(Wh, wcat_t, 512, 512, ZN, KCAT, 522);
    zpad_cols<<<(ZN * 22 + T - 1) / T, T>>>(wcat_t, KCAT, 1034, 22, ZN);
    transpose_f2h<<<dim3(16, 2),  tb>>>(Wprep, wprep_t, 64, 64, UU, MM, 0);
    transpose_f2h<<<dim3(3, 16),  tb>>>(Wr, wrw_t, 512, 512, 70, UU, 0);
    transpose_f2h<<<dim3(7, 16),  tb>>>(Ww, wrw_t + 70 * UU, 512, 512, 198, UU, 0);
    zfill_half<<<((RWNPAD - RWN) * UU + T - 1) / T, T>>>(wrw_t + RWN * UU,
                                                         (RWNPAD - RWN) * UU);
    transpose_f2h<<<dim3(16, 18), tb>>>(Wo, wo_t, 576, 576, UU, XON, 0);

    prep_misc<<<(BB * MM + T - 1) / T, T>>>(R0, br, bw);
    build_xcat<<<(int)(((size_t)BB * KCAT + T - 1) / T), T>>>(x_t, H0);

    // h_prep = R0 @ Wprep + bprep  -> half, straight into xcat cols [10,522)
    hgemm<64, 64, 2, 2, 2, 4, __half><<<dim3(UU / 64, BB / 64), 128>>>(
        r0h, wprep_t, bprep, xcat + INP, 64, MM, MM, KCAT, UU, 0.f);

    // z = Xcat @ Wcat + bl   (fp32 out)
    hgemm<128, 128, 2, 4, 4, 4, float><<<dim3(ZN / 128, BB / 128), 256>>>(
        xcat, wcat_t, bl, z, KCAT, KCAT, KCAT, ZN, ZN, 0.f);

    gates_kernel<<<(BB * UU + T - 1) / T, T>>>(C0);

    // [r_out | w_out] = h @ [Wr | Ww] + [br | bw]  (fp32 out)
    hgemm<64, 64, 2, 2, 2, 4, float><<<dim3(RWNPAD / 64, BB / 64), 128>>>(
        h, wrw_t, brw, rw, UU, UU, UU, RWN, RWN, 0.f);

    // addressing + memory update + R_t + w_read/w_write
    {
        size_t smem = ADDR_SMEM_FLOATS * sizeof(float);
        cudaFuncSetAttribute(ntm_addr_kernel,
                             cudaFuncAttributeMaxDynamicSharedMemorySize, (int)smem);
        ntm_addr_kernel<<<BB, 256, smem>>>(m0, A0, mt, Rt, wr, ww);
    }

    // y = [h | R_t] @ Wo + bo, clipped
    build_xo<<<(int)(((size_t)BB * XON + T - 1) / T), T>>>(Rt);
    hgemm<64, 64, 2, 2, 2, 4, float><<<dim3(UU / 64, BB / 64), 128>>>(
        xo, wo_t, bo, y, XON, XON, XON, UU, UU, CLIPV);
}

// round 6
// speedup vs baseline: 2.6057x; 1.0471x over previous
#include <cuda_runtime.h>
#include <cuda_fp16.h>
#include <math.h>
#include <stdint.h>

#define BB 2048
#define NN 256
#define MM 64
#define UU 512
#define INP 10
#define CLIPV 20.0f

#define KCAT 1056   // 10 + 512 + 512 = 1034, padded to mult of 32
#define ZN 2048
#define RWN 268     // 70 + 198
#define RWNPAD 384
#define XON 576     // 512 + 64

// ---------------- scratch (device globals, no allocation) ----------------
__device__ __align__(256) __half g_xcat[(size_t)BB * KCAT];    // A for z GEMM
__device__ __align__(256) __half g_wcat_t[(size_t)ZN * KCAT];  // gate-interleaved [n'][k]
__device__ __align__(256) float  g_blperm[ZN];
__device__ __align__(256) __half g_wrw_t[(size_t)RWNPAD * UU];
__device__ __align__(256) float  g_brw[RWNPAD];
__device__ __align__(256) float  g_rw[(size_t)BB * RWN];
__device__ __align__(256) __half g_xo[(size_t)BB * XON];       // [h | R_t] half
__device__ __align__(256) __half g_wo_t[(size_t)UU * XON];
__device__ __align__(256) __half g_wprep_t[(size_t)UU * MM];
__device__ __align__(256) __half g_r0h[(size_t)BB * MM];

// ---------------- helpers ----------------
__device__ __forceinline__ float sigm(float x) { return 1.0f / (1.0f + expf(-x)); }
__device__ __forceinline__ float softplus(float x) {
    return (x > 20.0f) ? x : log1pf(expf(x));
}

__device__ __forceinline__ void cpasync16(const void* smem_dst, const void* gsrc) {
    uint32_t d = (uint32_t)__cvta_generic_to_shared(smem_dst);
    asm volatile("cp.async.cg.shared.global [%0], [%1], 16;\n" :: "r"(d), "l"(gsrc));
}
__device__ __forceinline__ void cpasync_commit() {
    asm volatile("cp.async.commit_group;\n");
}
template<int NW> __device__ __forceinline__ void cpasync_wait() {
    asm volatile("cp.async.wait_group %0;\n" :: "n"(NW));
}
__device__ __forceinline__ void ldsm4(uint32_t& r0, uint32_t& r1, uint32_t& r2,
                                      uint32_t& r3, const __half* p) {
    uint32_t a = (uint32_t)__cvta_generic_to_shared(p);
    asm volatile("ldmatrix.sync.aligned.m8n8.x4.shared.b16 {%0,%1,%2,%3}, [%4];\n"
        : "=r"(r0), "=r"(r1), "=r"(r2), "=r"(r3) : "r"(a));
}
__device__ __forceinline__ void mma16816(float* d, const uint32_t* a,
                                         uint32_t b0, uint32_t b1) {
    asm volatile(
        "mma.sync.aligned.m16n8k16.row.col.f32.f16.f16.f32 "
        "{%0,%1,%2,%3}, {%4,%5,%6,%7}, {%8,%9}, {%0,%1,%2,%3};\n"
        : "+f"(d[0]), "+f"(d[1]), "+f"(d[2]), "+f"(d[3])
        : "r"(a[0]), "r"(a[1]), "r"(a[2]), "r"(a[3]), "r"(b0), "r"(b1));
}

__device__ __forceinline__ float blockReduceSum(float v, volatile float* red) {
    #pragma unroll
    for (int o = 16; o; o >>= 1) v += __shfl_xor_sync(0xffffffffu, v, o);
    if ((threadIdx.x & 31) == 0) red[threadIdx.x >> 5] = v;
    __syncthreads();
    if (threadIdx.x == 0) {
        float s = 0.f;
        #pragma unroll
        for (int i = 0; i < 8; i++) s += red[i];
        red[0] = s;
    }
    __syncthreads();
    float r = red[0];
    __syncthreads();
    return r;
}
__device__ __forceinline__ float blockReduceMax(float v, volatile float* red) {
    #pragma unroll
    for (int o = 16; o; o >>= 1) v = fmaxf(v, __shfl_xor_sync(0xffffffffu, v, o));
    if ((threadIdx.x & 31) == 0) red[threadIdx.x >> 5] = v;
    __syncthreads();
    if (threadIdx.x == 0) {
        float s = red[0];
        #pragma unroll
        for (int i = 1; i < 8; i++) s = fmaxf(s, red[i]);
        red[0] = s;
    }
    __syncthreads();
    float r = red[0];
    __syncthreads();
    return r;
}

// ---------------- fp16 tensor-core GEMM (generic) ----------------
template<int BM, int BN, int WM, int WN, int MT, int NT, typename OutT>
__global__ __launch_bounds__(WM * WN * 32, 2)
void hgemm(const __half* __restrict__ A, const __half* __restrict__ Bt,
           const float* __restrict__ bias, OutT* __restrict__ C,
           int Kdim, int lda, int ldb, int ldc, int Nreal, float clipv)
{
    constexpr int THREADS = WM * WN * 32;
    __shared__ __half As[2][BM * 40];
    __shared__ __half Bs[2][BN * 40];

    const int tid  = threadIdx.x;
    const int lane = tid & 31;
    const int warp = tid >> 5;
    const int wm = warp / WN;
    const int wn = warp % WN;
    const int brow = blockIdx.y * BM;
    const int bcol = blockIdx.x * BN;
    const int lq = lane >> 2;
    const int lr = lane & 3;

    const __half* Ablk = A + (size_t)brow * lda;
    const __half* Bblk = Bt + (size_t)bcol * ldb;

    float acc[MT][NT][4];
    #pragma unroll
    for (int i = 0; i < MT; i++)
        #pragma unroll
        for (int j = 0; j < NT; j++)
            #pragma unroll
            for (int t = 0; t < 4; t++) acc[i][j][t] = 0.f;

    const int a_row = (lane & 7) + ((lane >> 3) & 1) * 8;
    const int a_ch  = (lane >> 4) * 8;
    const int b_row = ((lane >> 4) & 1) * 8 + (lane & 7);
    const int b_ch  = ((lane >> 3) & 1) * 8;

    const int KT = Kdim / 32;

    auto loadTile = [&](int buf, int k0) {
        #pragma unroll
        for (int i = 0; i < (BM * 4) / THREADS; i++) {
            int ch = tid + i * THREADS;
            int r = ch >> 2, co = (ch & 3) * 8;
            cpasync16(&As[buf][r * 40 + co], Ablk + (size_t)r * lda + k0 + co);
        }
        #pragma unroll
        for (int i = 0; i < (BN * 4) / THREADS; i++) {
            int ch = tid + i * THREADS;
            int r = ch >> 2, co = (ch & 3) * 8;
            cpasync16(&Bs[buf][r * 40 + co], Bblk + (size_t)r * ldb + k0 + co);
        }
        cpasync_commit();
    };

    auto computeTile = [&](int buf) {
        const __half* as = As[buf];
        const __half* bs = Bs[buf];
        #pragma unroll
        for (int kk = 0; kk < 2; kk++) {
            uint32_t af[MT][4];
            #pragma unroll
            for (int mt = 0; mt < MT; mt++) {
                int row = wm * (MT * 16) + mt * 16 + a_row;
                ldsm4(af[mt][0], af[mt][1], af[mt][2], af[mt][3],
                      as + row * 40 + kk * 16 + a_ch);
            }
            uint32_t bf[NT][2];
            #pragma unroll
            for (int p = 0; p < NT / 2; p++) {
                int row = wn * (NT * 8) + p * 16 + b_row;
                ldsm4(bf[2 * p][0], bf[2 * p][1], bf[2 * p + 1][0], bf[2 * p + 1][1],
                      bs + row * 40 + kk * 16 + b_ch);
            }
            #pragma unroll
            for (int mt = 0; mt < MT; mt++)
                #pragma unroll
                for (int nt = 0; nt < NT; nt++)
                    mma16816(acc[mt][nt], af[mt], bf[nt][0], bf[nt][1]);
        }
    };

    loadTile(0, 0);
    for (int kt = 0; kt < KT - 1; kt++) {
        loadTile((kt + 1) & 1, (kt + 1) * 32);
        cpasync_wait<1>();
        __syncthreads();
        computeTile(kt & 1);
        __syncthreads();
    }
    cpasync_wait<0>();
    __syncthreads();
    computeTile((KT - 1) & 1);

    #pragma unroll
    for (int mt = 0; mt < MT; mt++) {
        #pragma unroll
        for (int hh = 0; hh < 2; hh++) {
            int row = brow + wm * (MT * 16) + mt * 16 + lq + hh * 8;
            #pragma unroll
            for (int nt = 0; nt < NT; nt++) {
                int col = bcol + wn * (NT * 8) + nt * 8 + lr * 2;
                if (col < Nreal) {
                    float v0 = acc[mt][nt][hh * 2 + 0] + bias[col];
                    float v1 = acc[mt][nt][hh * 2 + 1] + bias[col + 1];
                    if (clipv > 0.f) {
                        v0 = fminf(fmaxf(v0, -clipv), clipv);
                        v1 = fminf(fmaxf(v1, -clipv), clipv);
                    }
                    if (sizeof(OutT) == 2) {
                        *(__half2*)((__half*)C + (size_t)row * ldc + col) =
                            __halves2half2(__float2half_rn(v0), __float2half_rn(v1));
                    } else {
                        *(float2*)((float*)C + (size_t)row * ldc + col) =
                            make_float2(v0, v1);
                    }
                }
            }
        }
    }
}

// ---------------- z-GEMM with fused LSTM gate epilogue ----------------
// B rows are gate-interleaved: n' = 4*u + gate (gate: 0=i,1=f,2=g,3=o).
// Epilogue: pair lanes via shfl to gather (i,f,g,o), compute h, write half
// into xo[row*XON + u].
__global__ __launch_bounds__(256, 2)
void hgemm_gates(const __half* __restrict__ A, const __half* __restrict__ Bt,
                 const float* __restrict__ bias, const float* __restrict__ C0,
                 __half* __restrict__ xo)
{
    constexpr int BM = 128, BN = 128, WN = 4, MT = 4, NT = 4, THREADS = 256;
    __shared__ __half As[2][BM * 40];
    __shared__ __half Bs[2][BN * 40];

    const int tid  = threadIdx.x;
    const int lane = tid & 31;
    const int warp = tid >> 5;
    const int wm = warp / WN;
    const int wn = warp % WN;
    const int brow = blockIdx.y * BM;
    const int bcol = blockIdx.x * BN;
    const int lq = lane >> 2;
    const int lr = lane & 3;

    const __half* Ablk = A + (size_t)brow * KCAT;
    const __half* Bblk = Bt + (size_t)bcol * KCAT;

    float acc[MT][NT][4];
    #pragma unroll
    for (int i = 0; i < MT; i++)
        #pragma unroll
        for (int j = 0; j < NT; j++)
            #pragma unroll
            for (int t = 0; t < 4; t++) acc[i][j][t] = 0.f;

    const int a_row = (lane & 7) + ((lane >> 3) & 1) * 8;
    const int a_ch  = (lane >> 4) * 8;
    const int b_row = ((lane >> 4) & 1) * 8 + (lane & 7);
    const int b_ch  = ((lane >> 3) & 1) * 8;

    const int KT = KCAT / 32;

    auto loadTile = [&](int buf, int k0) {
        #pragma unroll
        for (int i = 0; i < (BM * 4) / THREADS; i++) {
            int ch = tid + i * THREADS;
            int r = ch >> 2, co = (ch & 3) * 8;
            cpasync16(&As[buf][r * 40 + co], Ablk + (size_t)r * KCAT + k0 + co);
        }
        #pragma unroll
        for (int i = 0; i < (BN * 4) / THREADS; i++) {
            int ch = tid + i * THREADS;
            int r = ch >> 2, co = (ch & 3) * 8;
            cpasync16(&Bs[buf][r * 40 + co], Bblk + (size_t)r * KCAT + k0 + co);
        }
        cpasync_commit();
    };

    auto computeTile = [&](int buf) {
        const __half* as = As[buf];
        const __half* bs = Bs[buf];
        #pragma unroll
        for (int kk = 0; kk < 2; kk++) {
            uint32_t af[MT][4];
            #pragma unroll
            for (int mt = 0; mt < MT; mt++) {
                int row = wm * (MT * 16) + mt * 16 + a_row;
                ldsm4(af[mt][0], af[mt][1], af[mt][2], af[mt][3],
                      as + row * 40 + kk * 16 + a_ch);
            }
            uint32_t bf[NT][2];
            #pragma unroll
            for (int p = 0; p < NT / 2; p++) {
                int row = wn * (NT * 8) + p * 16 + b_row;
                ldsm4(bf[2 * p][0], bf[2 * p][1], bf[2 * p + 1][0], bf[2 * p + 1][1],
                      bs + row * 40 + kk * 16 + b_ch);
            }
            #pragma unroll
            for (int mt = 0; mt < MT; mt++)
                #pragma unroll
                for (int nt = 0; nt < NT; nt++)
                    mma16816(acc[mt][nt], af[mt], bf[nt][0], bf[nt][1]);
        }
    };

    loadTile(0, 0);
    for (int kt = 0; kt < KT - 1; kt++) {
        loadTile((kt + 1) & 1, (kt + 1) * 32);
        cpasync_wait<1>();
        __syncthreads();
        computeTile(kt & 1);
        __syncthreads();
    }
    cpasync_wait<0>();
    __syncthreads();
    computeTile((KT - 1) & 1);

    // fused LSTM epilogue
    #pragma unroll
    for (int mt = 0; mt < MT; mt++) {
        #pragma unroll
        for (int hh = 0; hh < 2; hh++) {
            int row = brow + wm * (MT * 16) + mt * 16 + lq + hh * 8;
            #pragma unroll
            for (int nt = 0; nt < NT; nt++) {
                int col = bcol + wn * (NT * 8) + nt * 8 + lr * 2;
                float x0 = acc[mt][nt][hh * 2 + 0] + bias[col];
                float x1 = acc[mt][nt][hh * 2 + 1] + bias[col + 1];
                float y0 = __shfl_xor_sync(0xffffffffu, x0, 1);
                float y1 = __shfl_xor_sync(0xffffffffu, x1, 1);
                if ((lr & 1) == 0) {
                    // this lane: (i,f); partner: (g,o)
                    int u = col >> 2;
                    float c = sigm(x1) * C0[(size_t)row * UU + u]
                            + sigm(x0) * tanhf(y0);
                    float h = sigm(y1) * tanhf(c);   // |h|<1, clip no-op
                    xo[(size_t)row * XON + u] = __float2half_rn(h);
                }
            }
        }
    }
}

// ---------------- fused transpose prep (all weights, one kernel) ----------
__device__ __forceinline__ void doTrans(float (*tl)[33],
    const float* __restrict__ src, __half* __restrict__ dst,
    int R, int C, int ld, int kOff, int gx, int rem, bool perm)
{
    int bx = rem % gx, by = rem / gx;
    int cb = bx * 32, rb = by * 32;
    int x = threadIdx.x & 31, y = threadIdx.x >> 5;
    #pragma unroll
    for (int i = 0; i < 32; i += 8) {
        int r = rb + y + i, c = cb + x;
        tl[y + i][x] = (r < R && c < C) ? src[(size_t)r * C + c] : 0.f;
    }
    __syncthreads();
    #pragma unroll
    for (int i = 0; i < 32; i += 8) {
        int c = cb + y + i, r = rb + x;
        if (c < C && r < R) {
            int cr = perm ? (4 * (c & 511) + (c >> 9)) : c;
            dst[(size_t)cr * ld + kOff + r] = __float2half(tl[x][y + i]);
        }
    }
}

__global__ __launch_bounds__(256)
void prep_transpose(const float* __restrict__ Wx, const float* __restrict__ Wh,
                    const float* __restrict__ Wprep, const float* __restrict__ Wr,
                    const float* __restrict__ Ww, const float* __restrict__ Wo)
{
    __shared__ float tl[32][33];
    int bid = blockIdx.x;
    if (bid < 1088)      doTrans(tl, Wx, g_wcat_t, 522, 2048, KCAT, 0,   64, bid, true);
    else if (bid < 2112) doTrans(tl, Wh, g_wcat_t, 512, 2048, KCAT, 522, 64, bid - 1088, true);
    else if (bid < 2144) doTrans(tl, Wprep, g_wprep_t, 64, 512, MM, 0, 16, bid - 2112, false);
    else if (bid < 2192) doTrans(tl, Wr, g_wrw_t, 512, 70, UU, 0, 3, bid - 2144, false);
    else if (bid < 2304) doTrans(tl, Ww, g_wrw_t + 70 * UU, 512, 198, UU, 0, 7, bid - 2192, false);
    else                 doTrans(tl, Wo, g_wo_t, 576, 512, XON, 0, 16, bid - 2304, false);
}

// ---------------- fused elementwise prep ----------------
#define EN0 (BB * KCAT)       // xcat
#define EN1 (BB * MM)         // r0h
#define EN2 ZN                // blperm
#define EN3 RWNPAD            // brw
#define EN4 (ZN * 22)         // wcat_t k-pad
#define EN5 ((RWNPAD - RWN) * UU)  // wrw_t row pad
#define ETOT (EN0 + EN1 + EN2 + EN3 + EN4 + EN5)

__global__ __launch_bounds__(256)
void prep_elem(const float* __restrict__ x_t, const float* __restrict__ H0,
               const float* __restrict__ R0, const float* __restrict__ br,
               const float* __restrict__ bw, const float* __restrict__ bl)
{
    int idx = blockIdx.x * 256 + threadIdx.x;
    if (idx < EN0) {
        int b = idx / KCAT, c = idx % KCAT;
        if (c < INP)                 g_xcat[idx] = __float2half(x_t[b * INP + c]);
        else if (c >= 522 && c < 1034) g_xcat[idx] = __float2half(H0[(size_t)b * UU + (c - 522)]);
        else if (c >= 1034)          g_xcat[idx] = __ushort_as_half(0);
        // cols [10,522) written by hprep GEMM
        return;
    }
    idx -= EN0;
    if (idx < EN1) { g_r0h[idx] = __float2half(R0[idx]); return; }
    idx -= EN1;
    if (idx < EN2) {
        int u = idx >> 2, gate = idx & 3;
        g_blperm[idx] = bl[gate * UU + u];
        return;
    }
    idx -= EN2;
    if (idx < EN3) {
        float bv = 0.f;
        if (idx < 70) bv = br[idx];
        else if (idx < RWN) bv = bw[idx - 70];
        g_brw[idx] = bv;
        return;
    }
    idx -= EN3;
    if (idx < EN4) {
        int n = idx / 22, c = idx % 22;
        g_wcat_t[(size_t)n * KCAT + 1034 + c] = __ushort_as_half(0);
        return;
    }
    idx -= EN4;
    if (idx < EN5) {
        g_wrw_t[(size_t)RWN * UU + idx] = __ushort_as_half(0);
        return;
    }
}

// ---------------- NTM addressing + memory update (one CTA per batch row) ----
#define ADDR_SMEM_FLOATS (16640 + 256 + 64 + 256 + 256 + 256 + 64 + 64 + 32 + 8)

__global__ __launch_bounds__(256)
void ntm_addr_kernel(const float* __restrict__ m0, const float* __restrict__ A0,
                     float* __restrict__ out_mt, float* __restrict__ out_Rt,
                     float* __restrict__ out_wr, float* __restrict__ out_ww,
                     __half* __restrict__ xo)
{
    extern __shared__ float sm[];
    float* m0s    = sm;
    float* mnorm  = sm + 16640;
    float* ks     = mnorm + 256;
    float* wgs    = ks + 64;
    float* wread  = wgs + 256;
    float* wwrite = wread + 256;
    float* delv   = wwrite + 256;
    float* addv   = delv + 64;
    float* red    = addv + 64;
    float* scal   = red + 32;

    const int b = blockIdx.x;
    const int tid = threadIdx.x;
    const float4* m0g4 = (const float4*)(m0 + (size_t)b * (NN * MM));

    #pragma unroll 4
    for (int e4 = tid; e4 < NN * MM / 4; e4 += 256) {
        float4 v = m0g4[e4];
        int n = e4 >> 4, m = (e4 & 15) * 4;
        float* p = &m0s[n * 65 + m];
        p[0] = v.x; p[1] = v.y; p[2] = v.z; p[3] = v.w;
    }
    __syncthreads();

    {
        float s = 0.f;
        #pragma unroll 8
        for (int m = 0; m < MM; m++) { float v = m0s[tid * 65 + m]; s += v * v; }
        mnorm[tid] = sqrtf(s);
    }

    const float* rwrow = g_rw + (size_t)b * RWN;

    for (int hd = 0; hd < 2; hd++) {
        const float* head = rwrow + (hd ? 70 : 0);
        if (tid < 64) ks[tid] = tanhf(head[tid]);
        if (tid == 64) {
            scal[0] = softplus(head[64]);
            scal[1] = sigm(head[65]);
            float a = head[66], bq = head[67], cq = head[68];
            float mx = fmaxf(a, fmaxf(bq, cq));
            float e0 = expf(a - mx), e1 = expf(bq - mx), e2 = expf(cq - mx);
            float se = e0 + e1 + e2;
            scal[2] = e0 / se; scal[3] = e1 / se; scal[4] = e2 / se;
            scal[5] = softplus(head[69]);
        }
        __syncthreads();

        float kv = (tid < 64) ? ks[tid] : 0.f;
        float knorm = sqrtf(blockReduceSum(kv * kv, red));

        float ip = 0.f;
        #pragma unroll 8
        for (int m = 0; m < MM; m++) ip += m0s[tid * 65 + m] * ks[m];
        float Kv = ip / (knorm * mnorm[tid] + 1e-8f);
        float x = scal[0] * Kv;
        float mx = blockReduceMax(x, red);
        float p = expf(x - mx);
        float sump = blockReduceSum(p, red);
        float wc = p / sump;

        float gg = scal[1];
        float wgv = gg * wc + (1.f - gg) * A0[(size_t)hd * BB * NN + (size_t)b * NN + tid];
        wgs[tid] = wgv;
        __syncthreads();

        float s0 = scal[2], s1 = scal[3], s2 = scal[4], gamma = scal[5];
        float conv = s0 * wgv + s1 * wgs[(tid + 255) & 255] + s2 * wgs[(tid + 1) & 255];
        float wsh = powf(conv, gamma);
        float ssum = blockReduceSum(wsh, red);
        float w = wsh / ssum;

        float* dst = hd ? wwrite : wread;
        dst[tid] = w;
        (hd ? out_ww : out_wr)[(size_t)b * NN + tid] = w;
        __syncthreads();
    }

    if (tid < 64) {
        delv[tid] = sigm(rwrow[140 + tid]);
        addv[tid] = tanhf(rwrow[204 + tid]);
    }

    {
        int q = tid >> 6, m = tid & 63;
        float s = 0.f;
        #pragma unroll 8
        for (int n = q * 64; n < q * 64 + 64; n++) s += wread[n] * m0s[n * 65 + m];
        wgs[tid] = s;
    }
    __syncthreads();
    if (tid < 64) {
        float r = wgs[tid] + wgs[64 + tid] + wgs[128 + tid] + wgs[192 + tid];
        out_Rt[(size_t)b * MM + tid] = r;
        xo[(size_t)b * XON + UU + tid] = __float2half(r);
    }

    float4* mt4 = (float4*)(out_mt + (size_t)b * (NN * MM));
    #pragma unroll 4
    for (int e4 = tid; e4 < NN * MM / 4; e4 += 256) {
        int n = e4 >> 4, m = (e4 & 15) * 4;
        float ww = wwrite[n];
        const float* p = &m0s[n * 65 + m];
        float4 v;
        v.x = p[0] * (1.f - ww * delv[m + 0]) + ww * addv[m + 0];
        v.y = p[1] * (1.f - ww * delv[m + 1]) + ww * addv[m + 1];
        v.z = p[2] * (1.f - ww * delv[m + 2]) + ww * addv[m + 2];
        v.w = p[3] * (1.f - ww * delv[m + 3]) + ww * addv[m + 3];
        mt4[e4] = v;
    }
}

// ---------------- launch ----------------
extern "C" void kernel_launch(void* const* d_in, const int* in_sizes, int n_in,
                              void* d_out, int out_size)
{
    const float* x_t   = (const float*)d_in[0];
    const float* H0    = (const float*)d_in[1];
    const float* C0    = (const float*)d_in[2];
    const float* m0    = (const float*)d_in[3];
    const float* R0    = (const float*)d_in[4];
    const float* A0    = (const float*)d_in[5];
    const float* Wprep = (const float*)d_in[6];
    const float* bprep = (const float*)d_in[7];
    const float* Wx    = (const float*)d_in[8];
    const float* Wh    = (const float*)d_in[9];
    const float* bl    = (const float*)d_in[10];
    const float* Wr    = (const float*)d_in[11];
    const float* br    = (const float*)d_in[12];
    const float* Ww    = (const float*)d_in[13];
    const float* bw    = (const float*)d_in[14];
    const float* Wo    = (const float*)d_in[15];
    const float* bo    = (const float*)d_in[16];

    float* out = (float*)d_out;
    float* y  = out;
    float* mt = y + (size_t)BB * UU;
    float* Rt = mt + (size_t)BB * NN * MM;
    float* wr = Rt + (size_t)BB * MM;
    float* ww = wr + (size_t)BB * NN;

    __half *xcat, *wcat_t, *wrw_t, *xo, *wo_t, *wprep_t, *r0h;
    float *blperm, *brw, *rw;
    cudaGetSymbolAddress((void**)&xcat, g_xcat);
    cudaGetSymbolAddress((void**)&wcat_t, g_wcat_t);
    cudaGetSymbolAddress((void**)&blperm, g_blperm);
    cudaGetSymbolAddress((void**)&wrw_t, g_wrw_t);
    cudaGetSymbolAddress((void**)&brw, g_brw);
    cudaGetSymbolAddress((void**)&rw, g_rw);
    cudaGetSymbolAddress((void**)&xo, g_xo);
    cudaGetSymbolAddress((void**)&wo_t, g_wo_t);
    cudaGetSymbolAddress((void**)&wprep_t, g_wprep_t);
    cudaGetSymbolAddress((void**)&r0h, g_r0h);

    // 1) all weight transposes (gate-interleaved wcat)
    prep_transpose<<<2592, 256>>>(Wx, Wh, Wprep, Wr, Ww, Wo);

    // 2) all elementwise prep (xcat, r0h, biases, pads)
    prep_elem<<<(ETOT + 255) / 256, 256>>>(x_t, H0, R0, br, bw, bl);

    // 3) h_prep = R0 @ Wprep + bprep -> half, into xcat cols [10,522)
    hgemm<64, 64, 2, 2, 2, 4, __half><<<dim3(UU / 64, BB / 64), 128>>>(
        r0h, wprep_t, bprep, xcat + INP, 64, MM, MM, KCAT, UU, 0.f);

    // 4) z GEMM + fused LSTM gates -> h (half) into xo cols [0,512)
    hgemm_gates<<<dim3(ZN / 128, BB / 128), 256>>>(xcat, wcat_t, blperm, C0, xo);

    // 5) [r_out | w_out] = h @ [Wr | Ww] + [br | bw]  (A = xo, lda=XON)
    hgemm<64, 64, 2, 2, 2, 4, float><<<dim3(RWNPAD / 64, BB / 64), 128>>>(
        xo, wrw_t, brw, rw, UU, XON, UU, RWN, RWN, 0.f);

    // 6) addressing + memory update; writes Rt(fp32) + Rt(half into xo)
    {
        size_t smem = ADDR_SMEM_FLOATS * sizeof(float);
        cudaFuncSetAttribute(ntm_addr_kernel,
                             cudaFuncAttributeMaxDynamicSharedMemorySize, (int)smem);
        ntm_addr_kernel<<<BB, 256, smem>>>(m0, A0, mt, Rt, wr, ww, xo);
    }

    // 7) y = [h | R_t] @ Wo + bo, clipped
    hgemm<64, 64, 2, 2, 2, 4, float><<<dim3(UU / 64, BB / 64), 128>>>(
        xo, wo_t, bo, y, XON, XON, XON, UU, UU, CLIPV);
}

// round 8
// speedup vs baseline: 2.6882x; 1.0317x over previous
#include <cuda_runtime.h>
#include <cuda_fp16.h>
#include <math.h>
#include <stdint.h>

#define BB 2048
#define NN 256
#define MM 64
#define UU 512
#define INP 10
#define CLIPV 20.0f

#define KCAT 1056   // 10 + 512 + 512 = 1034, padded to mult of 32
#define ZN 2048
#define RWN 268     // 70 + 198
#define RWNPAD 384
#define XON 576     // 512 + 64

// ---------------- scratch (device globals, no allocation) ----------------
__device__ __align__(256) __half g_xcat[(size_t)BB * KCAT];    // A for z GEMM
__device__ __align__(256) __half g_wcat_t[(size_t)ZN * KCAT];  // gate-interleaved [n'][k]
__device__ __align__(256) float  g_blperm[ZN];
__device__ __align__(256) __half g_wrw_t[(size_t)RWNPAD * UU];
__device__ __align__(256) float  g_brw[RWNPAD];
__device__ __align__(256) float  g_rw[(size_t)BB * RWN];
__device__ __align__(256) __half g_xo[(size_t)BB * XON];       // [h | R_t] half
__device__ __align__(256) __half g_wo_t[(size_t)UU * XON];
__device__ __align__(256) __half g_wprep_t[(size_t)UU * MM];
__device__ __align__(256) __half g_r0h[(size_t)BB * MM];

// ---------------- helpers ----------------
__device__ __forceinline__ float sigm(float x) { return 1.0f / (1.0f + expf(-x)); }
__device__ __forceinline__ float softplus(float x) {
    return (x > 20.0f) ? x : log1pf(expf(x));
}

__device__ __forceinline__ void cpasync16(const void* smem_dst, const void* gsrc) {
    uint32_t d = (uint32_t)__cvta_generic_to_shared(smem_dst);
    asm volatile("cp.async.cg.shared.global [%0], [%1], 16;\n" :: "r"(d), "l"(gsrc));
}
__device__ __forceinline__ void cpasync_commit() {
    asm volatile("cp.async.commit_group;\n");
}
template<int NW> __device__ __forceinline__ void cpasync_wait() {
    asm volatile("cp.async.wait_group %0;\n" :: "n"(NW));
}
__device__ __forceinline__ void ldsm4(uint32_t& r0, uint32_t& r1, uint32_t& r2,
                                      uint32_t& r3, const __half* p) {
    uint32_t a = (uint32_t)__cvta_generic_to_shared(p);
    asm volatile("ldmatrix.sync.aligned.m8n8.x4.shared.b16 {%0,%1,%2,%3}, [%4];\n"
        : "=r"(r0), "=r"(r1), "=r"(r2), "=r"(r3) : "r"(a));
}
__device__ __forceinline__ void mma16816(float* d, const uint32_t* a,
                                         uint32_t b0, uint32_t b1) {
    asm volatile(
        "mma.sync.aligned.m16n8k16.row.col.f32.f16.f16.f32 "
        "{%0,%1,%2,%3}, {%4,%5,%6,%7}, {%8,%9}, {%0,%1,%2,%3};\n"
        : "+f"(d[0]), "+f"(d[1]), "+f"(d[2]), "+f"(d[3])
        : "r"(a[0]), "r"(a[1]), "r"(a[2]), "r"(a[3]), "r"(b0), "r"(b1));
}

__device__ __forceinline__ float blockReduceSum(float v, volatile float* red) {
    #pragma unroll
    for (int o = 16; o; o >>= 1) v += __shfl_xor_sync(0xffffffffu, v, o);
    if ((threadIdx.x & 31) == 0) red[threadIdx.x >> 5] = v;
    __syncthreads();
    if (threadIdx.x == 0) {
        float s = 0.f;
        #pragma unroll
        for (int i = 0; i < 8; i++) s += red[i];
        red[0] = s;
    }
    __syncthreads();
    float r = red[0];
    __syncthreads();
    return r;
}
__device__ __forceinline__ float blockReduceMax(float v, volatile float* red) {
    #pragma unroll
    for (int o = 16; o; o >>= 1) v = fmaxf(v, __shfl_xor_sync(0xffffffffu, v, o));
    if ((threadIdx.x & 31) == 0) red[threadIdx.x >> 5] = v;
    __syncthreads();
    if (threadIdx.x == 0) {
        float s = red[0];
        #pragma unroll
        for (int i = 1; i < 8; i++) s = fmaxf(s, red[i]);
        red[0] = s;
    }
    __syncthreads();
    float r = red[0];
    __syncthreads();
    return r;
}

// ---------------- fp16 tensor-core GEMM (3-stage cp.async pipeline) ----------
// C[M,N] = clip(A[M,K] @ Bt[N,K]^T + bias). Dynamic smem: 3*(BM+BN)*40 halves.
template<int BM, int BN, int WM, int WN, int MT, int NT, typename OutT>
__global__ __launch_bounds__(WM * WN * 32, 2)
void hgemm(const __half* __restrict__ A, const __half* __restrict__ Bt,
           const float* __restrict__ bias, OutT* __restrict__ C,
           int Kdim, int lda, int ldb, int ldc, int Nreal, float clipv)
{
    constexpr int THREADS = WM * WN * 32;
    extern __shared__ __half sh[];
    __half* AsB = sh;                    // 3 * BM * 40
    __half* BsB = sh + 3 * BM * 40;      // 3 * BN * 40

    const int tid  = threadIdx.x;
    const int lane = tid & 31;
    const int warp = tid >> 5;
    const int wm = warp / WN;
    const int wn = warp % WN;
    const int brow = blockIdx.y * BM;
    const int bcol = blockIdx.x * BN;
    const int lq = lane >> 2;
    const int lr = lane & 3;

    const __half* Ablk = A + (size_t)brow * lda;
    const __half* Bblk = Bt + (size_t)bcol * ldb;

    float acc[MT][NT][4];
    #pragma unroll
    for (int i = 0; i < MT; i++)
        #pragma unroll
        for (int j = 0; j < NT; j++)
            #pragma unroll
            for (int t = 0; t < 4; t++) acc[i][j][t] = 0.f;

    const int a_row = (lane & 7) + ((lane >> 3) & 1) * 8;
    const int a_ch  = (lane >> 4) * 8;
    const int b_row = ((lane >> 4) & 1) * 8 + (lane & 7);
    const int b_ch  = ((lane >> 3) & 1) * 8;

    const int KT = Kdim / 32;

    auto loadTile = [&](int buf, int k0) {
        __half* as = AsB + buf * BM * 40;
        __half* bs = BsB + buf * BN * 40;
        #pragma unroll
        for (int i = 0; i < (BM * 4) / THREADS; i++) {
            int ch = tid + i * THREADS;
            int r = ch >> 2, co = (ch & 3) * 8;
            cpasync16(&as[r * 40 + co], Ablk + (size_t)r * lda + k0 + co);
        }
        #pragma unroll
        for (int i = 0; i < (BN * 4) / THREADS; i++) {
            int ch = tid + i * THREADS;
            int r = ch >> 2, co = (ch & 3) * 8;
            cpasync16(&bs[r * 40 + co], Bblk + (size_t)r * ldb + k0 + co);
        }
        cpasync_commit();
    };

    auto computeTile = [&](int buf) {
        const __half* as = AsB + buf * BM * 40;
        const __half* bs = BsB + buf * BN * 40;
        #pragma unroll
        for (int kk = 0; kk < 2; kk++) {
            uint32_t af[MT][4];
            #pragma unroll
            for (int mt = 0; mt < MT; mt++) {
                int row = wm * (MT * 16) + mt * 16 + a_row;
                ldsm4(af[mt][0], af[mt][1], af[mt][2], af[mt][3],
                      as + row * 40 + kk * 16 + a_ch);
            }
            uint32_t bf[NT][2];
            #pragma unroll
            for (int p = 0; p < NT / 2; p++) {
                int row = wn * (NT * 8) + p * 16 + b_row;
                ldsm4(bf[2 * p][0], bf[2 * p][1], bf[2 * p + 1][0], bf[2 * p + 1][1],
                      bs + row * 40 + kk * 16 + b_ch);
            }
            #pragma unroll
            for (int mt = 0; mt < MT; mt++)
                #pragma unroll
                for (int nt = 0; nt < NT; nt++)
                    mma16816(acc[mt][nt], af[mt], bf[nt][0], bf[nt][1]);
        }
    };

    loadTile(0, 0);
    if (KT > 1) loadTile(1, 32); else cpasync_commit();
    for (int kt = 0; kt < KT; kt++) {
        cpasync_wait<1>();
        __syncthreads();
        computeTile(kt % 3);
        int nk = kt + 2;
        if (nk < KT) loadTile(nk % 3, nk * 32); else cpasync_commit();
    }

    #pragma unroll
    for (int mt = 0; mt < MT; mt++) {
        #pragma unroll
        for (int hh = 0; hh < 2; hh++) {
            int row = brow + wm * (MT * 16) + mt * 16 + lq + hh * 8;
            #pragma unroll
            for (int nt = 0; nt < NT; nt++) {
                int col = bcol + wn * (NT * 8) + nt * 8 + lr * 2;
                if (col < Nreal) {
                    float v0 = acc[mt][nt][hh * 2 + 0] + bias[col];
                    float v1 = acc[mt][nt][hh * 2 + 1] + bias[col + 1];
                    if (clipv > 0.f) {
                        v0 = fminf(fmaxf(v0, -clipv), clipv);
                        v1 = fminf(fmaxf(v1, -clipv), clipv);
                    }
                    if (sizeof(OutT) == 2) {
                        *(__half2*)((__half*)C + (size_t)row * ldc + col) =
                            __halves2half2(__float2half_rn(v0), __float2half_rn(v1));
                    } else {
                        *(float2*)((float*)C + (size_t)row * ldc + col) =
                            make_float2(v0, v1);
                    }
                }
            }
        }
    }
}

// ---------------- z-GEMM with fused LSTM gate epilogue (3-stage) ----------
// B rows gate-interleaved: n' = 4*u + gate (0=i,1=f,2=g,3=o).
__global__ __launch_bounds__(256, 2)
void hgemm_gates(const __half* __restrict__ A, const __half* __restrict__ Bt,
                 const float* __restrict__ bias, const float* __restrict__ C0,
                 __half* __restrict__ xo)
{
    constexpr int BM = 128, BN = 128, WN = 4, MT = 4, NT = 4, THREADS = 256;
    extern __shared__ __half sh[];
    __half* AsB = sh;
    __half* BsB = sh + 3 * BM * 40;

    const int tid  = threadIdx.x;
    const int lane = tid & 31;
    const int warp = tid >> 5;
    const int wm = warp / WN;
    const int wn = warp % WN;
    const int brow = blockIdx.y * BM;
    const int bcol = blockIdx.x * BN;
    const int lq = lane >> 2;
    const int lr = lane & 3;

    const __half* Ablk = A + (size_t)brow * KCAT;
    const __half* Bblk = Bt + (size_t)bcol * KCAT;

    float acc[MT][NT][4];
    #pragma unroll
    for (int i = 0; i < MT; i++)
        #pragma unroll
        for (int j = 0; j < NT; j++)
            #pragma unroll
            for (int t = 0; t < 4; t++) acc[i][j][t] = 0.f;

    const int a_row = (lane & 7) + ((lane >> 3) & 1) * 8;
    const int a_ch  = (lane >> 4) * 8;
    const int b_row = ((lane >> 4) & 1) * 8 + (lane & 7);
    const int b_ch  = ((lane >> 3) & 1) * 8;

    const int KT = KCAT / 32;

    auto loadTile = [&](int buf, int k0) {
        __half* as = AsB + buf * BM * 40;
        __half* bs = BsB + buf * BN * 40;
        #pragma unroll
        for (int i = 0; i < (BM * 4) / THREADS; i++) {
            int ch = tid + i * THREADS;
            int r = ch >> 2, co = (ch & 3) * 8;
            cpasync16(&as[r * 40 + co], Ablk + (size_t)r * KCAT + k0 + co);
        }
        #pragma unroll
        for (int i = 0; i < (BN * 4) / THREADS; i++) {
            int ch = tid + i * THREADS;
            int r = ch >> 2, co = (ch & 3) * 8;
            cpasync16(&bs[r * 40 + co], Bblk + (size_t)r * KCAT + k0 + co);
        }
        cpasync_commit();
    };

    auto computeTile = [&](int buf) {
        const __half* as = AsB + buf * BM * 40;
        const __half* bs = BsB + buf * BN * 40;
        #pragma unroll
        for (int kk = 0; kk < 2; kk++) {
            uint32_t af[MT][4];
            #pragma unroll
            for (int mt = 0; mt < MT; mt++) {
                int row = wm * (MT * 16) + mt * 16 + a_row;
                ldsm4(af[mt][0], af[mt][1], af[mt][2], af[mt][3],
                      as + row * 40 + kk * 16 + a_ch);
            }
            uint32_t bf[NT][2];
            #pragma unroll
            for (int p = 0; p < NT / 2; p++) {
                int row = wn * (NT * 8) + p * 16 + b_row;
                ldsm4(bf[2 * p][0], bf[2 * p][1], bf[2 * p + 1][0], bf[2 * p + 1][1],
                      bs + row * 40 + kk * 16 + b_ch);
            }
            #pragma unroll
            for (int mt = 0; mt < MT; mt++)
                #pragma unroll
                for (int nt = 0; nt < NT; nt++)
                    mma16816(acc[mt][nt], af[mt], bf[nt][0], bf[nt][1]);
        }
    };

    loadTile(0, 0);
    loadTile(1, 32);
    for (int kt = 0; kt < KT; kt++) {
        cpasync_wait<1>();
        __syncthreads();
        computeTile(kt % 3);
        int nk = kt + 2;
        if (nk < KT) loadTile(nk % 3, nk * 32); else cpasync_commit();
    }

    // fused LSTM epilogue
    #pragma unroll
    for (int mt = 0; mt < MT; mt++) {
        #pragma unroll
        for (int hh = 0; hh < 2; hh++) {
            int row = brow + wm * (MT * 16) + mt * 16 + lq + hh * 8;
            #pragma unroll
            for (int nt = 0; nt < NT; nt++) {
                int col = bcol + wn * (NT * 8) + nt * 8 + lr * 2;
                float x0 = acc[mt][nt][hh * 2 + 0] + bias[col];
                float x1 = acc[mt][nt][hh * 2 + 1] + bias[col + 1];
                float y0 = __shfl_xor_sync(0xffffffffu, x0, 1);
                float y1 = __shfl_xor_sync(0xffffffffu, x1, 1);
                if ((lr & 1) == 0) {
                    int u = col >> 2;
                    float c = sigm(x1) * C0[(size_t)row * UU + u]
                            + sigm(x0) * tanhf(y0);
                    float h = sigm(y1) * tanhf(c);   // |h|<1, clip no-op
                    xo[(size_t)row * XON + u] = __float2half_rn(h);
                }
            }
        }
    }
}

// ---------------- fused transpose prep (all weights, one kernel) ----------
__device__ __forceinline__ void doTrans(float (*tl)[33],
    const float* __restrict__ src, __half* __restrict__ dst,
    int R, int C, int ld, int kOff, int gx, int rem, bool perm)
{
    int bx = rem % gx, by = rem / gx;
    int cb = bx * 32, rb = by * 32;
    int x = threadIdx.x & 31, y = threadIdx.x >> 5;
    #pragma unroll
    for (int i = 0; i < 32; i += 8) {
        int r = rb + y + i, c = cb + x;
        tl[y + i][x] = (r < R && c < C) ? src[(size_t)r * C + c] : 0.f;
    }
    __syncthreads();
    #pragma unroll
    for (int i = 0; i < 32; i += 8) {
        int c = cb + y + i, r = rb + x;
        if (c < C && r < R) {
            int cr = perm ? (4 * (c & 511) + (c >> 9)) : c;
            dst[(size_t)cr * ld + kOff + r] = __float2half(tl[x][y + i]);
        }
    }
}

__global__ __launch_bounds__(256)
void prep_transpose(const float* __restrict__ Wx, const float* __restrict__ Wh,
                    const float* __restrict__ Wprep, const float* __restrict__ Wr,
                    const float* __restrict__ Ww, const float* __restrict__ Wo)
{
    __shared__ float tl[32][33];
    int bid = blockIdx.x;
    if (bid < 1088)      doTrans(tl, Wx, g_wcat_t, 522, 2048, KCAT, 0,   64, bid, true);
    else if (bid < 2112) doTrans(tl, Wh, g_wcat_t, 512, 2048, KCAT, 522, 64, bid - 1088, true);
    else if (bid < 2144) doTrans(tl, Wprep, g_wprep_t, 64, 512, MM, 0, 16, bid - 2112, false);
    else if (bid < 2192) doTrans(tl, Wr, g_wrw_t, 512, 70, UU, 0, 3, bid - 2144, false);
    else if (bid < 2304) doTrans(tl, Ww, g_wrw_t + 70 * UU, 512, 198, UU, 0, 7, bid - 2192, false);
    else                 doTrans(tl, Wo, g_wo_t, 576, 512, XON, 0, 16, bid - 2304, false);
}

// ---------------- fused elementwise prep ----------------
#define EN0 (BB * KCAT)
#define EN1 (BB * MM)
#define EN2 ZN
#define EN3 RWNPAD
#define EN4 (ZN * 22)
#define EN5 ((RWNPAD - RWN) * UU)
#define ETOT (EN0 + EN1 + EN2 + EN3 + EN4 + EN5)

__global__ __launch_bounds__(256)
void prep_elem(const float* __restrict__ x_t, const float* __restrict__ H0,
               const float* __restrict__ R0, const float* __restrict__ br,
               const float* __restrict__ bw, const float* __restrict__ bl)
{
    int idx = blockIdx.x * 256 + threadIdx.x;
    if (idx < EN0) {
        int b = idx / KCAT, c = idx % KCAT;
        if (c < INP)                   g_xcat[idx] = __float2half(x_t[b * INP + c]);
        else if (c >= 522 && c < 1034) g_xcat[idx] = __float2half(H0[(size_t)b * UU + (c - 522)]);
        else if (c >= 1034)            g_xcat[idx] = __ushort_as_half(0);
        return;
    }
    idx -= EN0;
    if (idx < EN1) { g_r0h[idx] = __float2half(R0[idx]); return; }
    idx -= EN1;
    if (idx < EN2) {
        int u = idx >> 2, gate = idx & 3;
        g_blperm[idx] = bl[gate * UU + u];
        return;
    }
    idx -= EN2;
    if (idx < EN3) {
        float bv = 0.f;
        if (idx < 70) bv = br[idx];
        else if (idx < RWN) bv = bw[idx - 70];
        g_brw[idx] = bv;
        return;
    }
    idx -= EN3;
    if (idx < EN4) {
        int n = idx / 22, c = idx % 22;
        g_wcat_t[(size_t)n * KCAT + 1034 + c] = __ushort_as_half(0);
        return;
    }
    idx -= EN4;
    if (idx < EN5) {
        g_wrw_t[(size_t)RWN * UU + idx] = __ushort_as_half(0);
        return;
    }
}

// ---------------- NTM addressing + memory update (one CTA per batch row) ----
#define ADDR_SMEM_FLOATS (16640 + 256 + 64 + 256 + 256 + 256 + 64 + 64 + 32 + 8)

__global__ __launch_bounds__(256)
void ntm_addr_kernel(const float* __restrict__ m0, const float* __restrict__ A0,
                     float* __restrict__ out_mt, float* __restrict__ out_Rt,
                     float* __restrict__ out_wr, float* __restrict__ out_ww,
                     __half* __restrict__ xo)
{
    extern __shared__ float sm[];
    float* m0s    = sm;
    float* mnorm  = sm + 16640;
    float* ks     = mnorm + 256;
    float* wgs    = ks + 64;
    float* wread  = wgs + 256;
    float* wwrite = wread + 256;
    float* delv   = wwrite + 256;
    float* addv   = delv + 64;
    float* red    = addv + 64;
    float* scal   = red + 32;

    const int b = blockIdx.x;
    const int tid = threadIdx.x;
    const float4* m0g4 = (const float4*)(m0 + (size_t)b * (NN * MM));

    #pragma unroll 4
    for (int e4 = tid; e4 < NN * MM / 4; e4 += 256) {
        float4 v = m0g4[e4];
        int n = e4 >> 4, m = (e4 & 15) * 4;
        float* p = &m0s[n * 65 + m];
        p[0] = v.x; p[1] = v.y; p[2] = v.z; p[3] = v.w;
    }
    __syncthreads();

    {
        float s = 0.f;
        #pragma unroll 8
        for (int m = 0; m < MM; m++) { float v = m0s[tid * 65 + m]; s += v * v; }
        mnorm[tid] = sqrtf(s);
    }

    const float* rwrow = g_rw + (size_t)b * RWN;

    for (int hd = 0; hd < 2; hd++) {
        const float* head = rwrow + (hd ? 70 : 0);
        if (tid < 64) ks[tid] = tanhf(head[tid]);
        if (tid == 64) {
            scal[0] = softplus(head[64]);
            scal[1] = sigm(head[65]);
            float a = head[66], bq = head[67], cq = head[68];
            float mx = fmaxf(a, fmaxf(bq, cq));
            float e0 = expf(a - mx), e1 = expf(bq - mx), e2 = expf(cq - mx);
            float se = e0 + e1 + e2;
            scal[2] = e0 / se; scal[3] = e1 / se; scal[4] = e2 / se;
            scal[5] = softplus(head[69]);
        }
        __syncthreads();

        float kv = (tid < 64) ? ks[tid] : 0.f;
        float knorm = sqrtf(blockReduceSum(kv * kv, red));

        float ip = 0.f;
        #pragma unroll 8
        for (int m = 0; m < MM; m++) ip += m0s[tid * 65 + m] * ks[m];
        float Kv = ip / (knorm * mnorm[tid] + 1e-8f);
        float x = scal[0] * Kv;
        float mx = blockReduceMax(x, red);
        float p = expf(x - mx);
        float sump = blockReduceSum(p, red);
        float wc = p / sump;

        float gg = scal[1];
        float wgv = gg * wc + (1.f - gg) * A0[(size_t)hd * BB * NN + (size_t)b * NN + tid];
        wgs[tid] = wgv;
        __syncthreads();

        float s0 = scal[2], s1 = scal[3], s2 = scal[4], gamma = scal[5];
        float conv = s0 * wgv + s1 * wgs[(tid + 255) & 255] + s2 * wgs[(tid + 1) & 255];
        float wsh = powf(conv, gamma);
        float ssum = blockReduceSum(wsh, red);
        float w = wsh / ssum;

        float* dst = hd ? wwrite : wread;
        dst[tid] = w;
        (hd ? out_ww : out_wr)[(size_t)b * NN + tid] = w;
        __syncthreads();
    }

    if (tid < 64) {
        delv[tid] = sigm(rwrow[140 + tid]);
        addv[tid] = tanhf(rwrow[204 + tid]);
    }

    {
        int q = tid >> 6, m = tid & 63;
        float s = 0.f;
        #pragma unroll 8
        for (int n = q * 64; n < q * 64 + 64; n++) s += wread[n] * m0s[n * 65 + m];
        wgs[tid] = s;
    }
    __syncthreads();
    if (tid < 64) {
        float r = wgs[tid] + wgs[64 + tid] + wgs[128 + tid] + wgs[192 + tid];
        out_Rt[(size_t)b * MM + tid] = r;
        xo[(size_t)b * XON + UU + tid] = __float2half(r);
    }

    float4* mt4 = (float4*)(out_mt + (size_t)b * (NN * MM));
    #pragma unroll 4
    for (int e4 = tid; e4 < NN * MM / 4; e4 += 256) {
        int n = e4 >> 4, m = (e4 & 15) * 4;
        float ww = wwrite[n];
        const float* p = &m0s[n * 65 + m];
        float4 v;
        v.x = p[0] * (1.f - ww * delv[m + 0]) + ww * addv[m + 0];
        v.y = p[1] * (1.f - ww * delv[m + 1]) + ww * addv[m + 1];
        v.z = p[2] * (1.f - ww * delv[m + 2]) + ww * addv[m + 2];
        v.w = p[3] * (1.f - ww * delv[m + 3]) + ww * addv[m + 3];
        mt4[e4] = v;
    }
}

// ---------------- launch ----------------
extern "C" void kernel_launch(void* const* d_in, const int* in_sizes, int n_in,
                              void* d_out, int out_size)
{
    const float* x_t   = (const float*)d_in[0];
    const float* H0    = (const float*)d_in[1];
    const float* C0    = (const float*)d_in[2];
    const float* m0    = (const float*)d_in[3];
    const float* R0    = (const float*)d_in[4];
    const float* A0    = (const float*)d_in[5];
    const float* Wprep = (const float*)d_in[6];
    const float* bprep = (const float*)d_in[7];
    const float* Wx    = (const float*)d_in[8];
    const float* Wh    = (const float*)d_in[9];
    const float* bl    = (const float*)d_in[10];
    const float* Wr    = (const float*)d_in[11];
    const float* br    = (const float*)d_in[12];
    const float* Ww    = (const float*)d_in[13];
    const float* bw    = (const float*)d_in[14];
    const float* Wo    = (const float*)d_in[15];
    const float* bo    = (const float*)d_in[16];

    float* out = (float*)d_out;
    float* y  = out;
    float* mt = y + (size_t)BB * UU;
    float* Rt = mt + (size_t)BB * NN * MM;
    float* wr = Rt + (size_t)BB * MM;
    float* ww = wr + (size_t)BB * NN;

    __half *xcat, *wcat_t, *wrw_t, *xo, *wo_t, *wprep_t, *r0h;
    float *blperm, *brw, *rw;
    cudaGetSymbolAddress((void**)&xcat, g_xcat);
    cudaGetSymbolAddress((void**)&wcat_t, g_wcat_t);
    cudaGetSymbolAddress((void**)&blperm, g_blperm);
    cudaGetSymbolAddress((void**)&wrw_t, g_wrw_t);
    cudaGetSymbolAddress((void**)&brw, g_brw);
    cudaGetSymbolAddress((void**)&rw, g_rw);
    cudaGetSymbolAddress((void**)&xo, g_xo);
    cudaGetSymbolAddress((void**)&wo_t, g_wo_t);
    cudaGetSymbolAddress((void**)&wprep_t, g_wprep_t);
    cudaGetSymbolAddress((void**)&r0h, g_r0h);

    const int SM_GATES = 3 * (128 + 128) * 40 * (int)sizeof(__half);  // 61440
    const int SM_64    = 3 * (64 + 64) * 40 * (int)sizeof(__half);    // 30720
    cudaFuncSetAttribute(hgemm_gates,
        cudaFuncAttributeMaxDynamicSharedMemorySize, SM_GATES);
    cudaFuncSetAttribute(hgemm<64, 64, 2, 2, 2, 4, __half>,
        cudaFuncAttributeMaxDynamicSharedMemorySize, SM_64);
    cudaFuncSetAttribute(hgemm<64, 64, 2, 2, 2, 4, float>,
        cudaFuncAttributeMaxDynamicSharedMemorySize, SM_64);

    // 1) all weight transposes (gate-interleaved wcat)
    prep_transpose<<<2592, 256>>>(Wx, Wh, Wprep, Wr, Ww, Wo);

    // 2) all elementwise prep (xcat, r0h, biases, pads)
    prep_elem<<<(ETOT + 255) / 256, 256>>>(x_t, H0, R0, br, bw, bl);

    // 3) h_prep = R0 @ Wprep + bprep -> half, into xcat cols [10,522)
    hgemm<64, 64, 2, 2, 2, 4, __half><<<dim3(UU / 64, BB / 64), 128, SM_64>>>(
        r0h, wprep_t, bprep, xcat + INP, 64, MM, MM, KCAT, UU, 0.f);

    // 4) z GEMM + fused LSTM gates -> h (half) into xo cols [0,512)
    hgemm_gates<<<dim3(ZN / 128, BB / 128), 256, SM_GATES>>>(
        xcat, wcat_t, blperm, C0, xo);

    // 5) [r_out | w_out] = h @ [Wr | Ww] + [br | bw]
    hgemm<64, 64, 2, 2, 2, 4, float><<<dim3(RWNPAD / 64, BB / 64), 128, SM_64>>>(
        xo, wrw_t, brw, rw, UU, XON, UU, RWN, RWN, 0.f);

    // 6) addressing + memory update; writes Rt(fp32) + Rt(half into xo)
    {
        size_t smem = ADDR_SMEM_FLOATS * sizeof(float);
        cudaFuncSetAttribute(ntm_addr_kernel,
                             cudaFuncAttributeMaxDynamicSharedMemorySize, (int)smem);
        ntm_addr_kernel<<<BB, 256, smem>>>(m0, A0, mt, Rt, wr, ww, xo);
    }

    // 7) y = [h | R_t] @ Wo + bo, clipped
    hgemm<64, 64, 2, 2, 2, 4, float><<<dim3(UU / 64, BB / 64), 128, SM_64>>>(
        xo, wo_t, bo, y, XON, XON, XON, UU, UU, CLIPV);
}

// round 10
// speedup vs baseline: 2.7318x; 1.0162x over previous
#include <cuda_runtime.h>
#include <cuda_fp16.h>
#include <math.h>
#include <stdint.h>

#define BB 2048
#define NN 256
#define MM 64
#define UU 512
#define INP 10
#define CLIPV 20.0f

#define K2 1088     // 1034 padded to mult of 64
#define ZN 2048
#define RWN 268
#define RWNPAD 384
#define XON 576

// ---------------- scratch (device globals, no allocation) ----------------
__device__ __align__(256) __half g_xcat[(size_t)BB * K2];
__device__ __align__(256) __half g_wcat_t[(size_t)ZN * K2];  // gate-interleaved [n'][k]
__device__ __align__(256) float  g_blperm[ZN];
__device__ __align__(256) __half g_wrw_t[(size_t)RWNPAD * UU];
__device__ __align__(256) float  g_brw[RWNPAD];
__device__ __align__(256) float  g_rw[(size_t)BB * RWN];
__device__ __align__(256) __half g_xo[(size_t)BB * XON];
__device__ __align__(256) __half g_wo_t[(size_t)UU * XON];
__device__ __align__(256) __half g_wprep_t[(size_t)UU * MM];
__device__ __align__(256) __half g_r0h[(size_t)BB * MM];

// ---------------- helpers ----------------
__device__ __forceinline__ float sigm(float x) { return 1.0f / (1.0f + expf(-x)); }
__device__ __forceinline__ float softplus(float x) {
    return (x > 20.0f) ? x : log1pf(expf(x));
}

__device__ __forceinline__ void cpasync16p(const void* smem_dst, const void* gsrc) {
    uint32_t d = (uint32_t)__cvta_generic_to_shared(smem_dst);
    asm volatile("cp.async.cg.shared.global [%0], [%1], 16;\n" :: "r"(d), "l"(gsrc));
}
__device__ __forceinline__ void cpasync_commit() {
    asm volatile("cp.async.commit_group;\n");
}
template<int NW> __device__ __forceinline__ void cpasync_wait() {
    asm volatile("cp.async.wait_group %0;\n" :: "n"(NW));
}
__device__ __forceinline__ void ldsm4(uint32_t& r0, uint32_t& r1, uint32_t& r2,
                                      uint32_t& r3, const __half* p) {
    uint32_t a = (uint32_t)__cvta_generic_to_shared(p);
    asm volatile("ldmatrix.sync.aligned.m8n8.x4.shared.b16 {%0,%1,%2,%3}, [%4];\n"
        : "=r"(r0), "=r"(r1), "=r"(r2), "=r"(r3) : "r"(a));
}
__device__ __forceinline__ void mma16816(float* d, const uint32_t* a,
                                         uint32_t b0, uint32_t b1) {
    asm volatile(
        "mma.sync.aligned.m16n8k16.row.col.f32.f16.f16.f32 "
        "{%0,%1,%2,%3}, {%4,%5,%6,%7}, {%8,%9}, {%0,%1,%2,%3};\n"
        : "+f"(d[0]), "+f"(d[1]), "+f"(d[2]), "+f"(d[3])
        : "r"(a[0]), "r"(a[1]), "r"(a[2]), "r"(a[3]), "r"(b0), "r"(b1));
}

__device__ __forceinline__ float blockReduceSum(float v, volatile float* red) {
    #pragma unroll
    for (int o = 16; o; o >>= 1) v += __shfl_xor_sync(0xffffffffu, v, o);
    if ((threadIdx.x & 31) == 0) red[threadIdx.x >> 5] = v;
    __syncthreads();
    if (threadIdx.x == 0) {
        float s = 0.f;
        #pragma unroll
        for (int i = 0; i < 8; i++) s += red[i];
        red[0] = s;
    }
    __syncthreads();
    float r = red[0];
    __syncthreads();
    return r;
}
__device__ __forceinline__ float blockReduceMax(float v, volatile float* red) {
    #pragma unroll
    for (int o = 16; o; o >>= 1) v = fmaxf(v, __shfl_xor_sync(0xffffffffu, v, o));
    if ((threadIdx.x & 31) == 0) red[threadIdx.x >> 5] = v;
    __syncthreads();
    if (threadIdx.x == 0) {
        float s = red[0];
        #pragma unroll
        for (int i = 1; i < 8; i++) s = fmaxf(s, red[i]);
        red[0] = s;
    }
    __syncthreads();
    float r = red[0];
    __syncthreads();
    return r;
}

// ================= z-GEMM (mma.sync, BK=64, 3-stage) + fused LSTM gates ====
// B rows gate-interleaved: n' = 4*u + gate (0=i,1=f,2=g,3=o).
#define GSTRIDE 72                  // halves per smem row (144B, 16B-mult, conflict-free)
#define GSTG (128 * GSTRIDE)        // halves per matrix per stage
#define G_SMEM (3 * 2 * GSTG * (int)sizeof(__half))   // 110592 B
#define GKT (K2 / 64)               // 17 chunks

__global__ __launch_bounds__(256, 2)
void hgemm_gates(const __half* __restrict__ A, const __half* __restrict__ Bt,
                 const float* __restrict__ bias, const float* __restrict__ C0,
                 __half* __restrict__ xo)
{
    constexpr int MT = 4, NT = 4, WN = 4;
    extern __shared__ __half sh[];
    __half* AsB = sh;
    __half* BsB = sh + 3 * GSTG;

    const int tid  = threadIdx.x;
    const int lane = tid & 31;
    const int warp = tid >> 5;
    const int wm = warp / WN;
    const int wn = warp % WN;
    const int brow = blockIdx.y * 128;
    const int bcol = blockIdx.x * 128;
    const int lq = lane >> 2;
    const int lr = lane & 3;

    const __half* Ablk = A + (size_t)brow * K2;
    const __half* Bblk = Bt + (size_t)bcol * K2;

    float acc[MT][NT][4];
    #pragma unroll
    for (int i = 0; i < MT; i++)
        #pragma unroll
        for (int j = 0; j < NT; j++)
            #pragma unroll
            for (int t = 0; t < 4; t++) acc[i][j][t] = 0.f;

    const int a_row = (lane & 7) + ((lane >> 3) & 1) * 8;
    const int a_ch  = (lane >> 4) * 8;
    const int b_row = ((lane >> 4) & 1) * 8 + (lane & 7);
    const int b_ch  = ((lane >> 3) & 1) * 8;

    // load 64-wide K chunk c into stage buf
    auto loadChunk = [&](int buf, int c) {
        __half* as = AsB + buf * GSTG;
        __half* bs = BsB + buf * GSTG;
        #pragma unroll
        for (int it = 0; it < 4; it++) {
            int id = tid + it * 256;            // 0..1023
            int row = id >> 3, c16 = id & 7;
            cpasync16p(&as[row * GSTRIDE + c16 * 8],
                       Ablk + (size_t)row * K2 + c * 64 + c16 * 8);
        }
        #pragma unroll
        for (int it = 0; it < 4; it++) {
            int id = tid + it * 256;
            int row = id >> 3, c16 = id & 7;
            cpasync16p(&bs[row * GSTRIDE + c16 * 8],
                       Bblk + (size_t)row * K2 + c * 64 + c16 * 8);
        }
        cpasync_commit();
    };

    auto computeChunk = [&](int buf) {
        const __half* as = AsB + buf * GSTG;
        const __half* bs = BsB + buf * GSTG;
        #pragma unroll
        for (int kk = 0; kk < 4; kk++) {
            uint32_t af[MT][4];
            #pragma unroll
            for (int mt = 0; mt < MT; mt++) {
                int row = wm * 64 + mt * 16 + a_row;
                ldsm4(af[mt][0], af[mt][1], af[mt][2], af[mt][3],
                      as + row * GSTRIDE + kk * 16 + a_ch);
            }
            uint32_t bf[NT][2];
            #pragma unroll
            for (int p = 0; p < NT / 2; p++) {
                int row = wn * 32 + p * 16 + b_row;
                ldsm4(bf[2 * p][0], bf[2 * p][1], bf[2 * p + 1][0], bf[2 * p + 1][1],
                      bs + row * GSTRIDE + kk * 16 + b_ch);
            }
            #pragma unroll
            for (int mt = 0; mt < MT; mt++)
                #pragma unroll
                for (int nt = 0; nt < NT; nt++)
                    mma16816(acc[mt][nt], af[mt], bf[nt][0], bf[nt][1]);
        }
    };

    loadChunk(0, 0);
    loadChunk(1, 1);
    for (int kt = 0; kt < GKT; kt++) {
        cpasync_wait<1>();
        __syncthreads();
        computeChunk(kt % 3);
        int nk = kt + 2;
        if (nk < GKT) loadChunk(nk % 3, nk);
        else cpasync_commit();
    }

    // fused LSTM epilogue (gate-interleaved columns)
    #pragma unroll
    for (int mt = 0; mt < MT; mt++) {
        #pragma unroll
        for (int hh = 0; hh < 2; hh++) {
            int row = brow + wm * 64 + mt * 16 + lq + hh * 8;
            #pragma unroll
            for (int nt = 0; nt < NT; nt++) {
                int col = bcol + wn * 32 + nt * 8 + lr * 2;
                float x0 = acc[mt][nt][hh * 2 + 0] + bias[col];
                float x1 = acc[mt][nt][hh * 2 + 1] + bias[col + 1];
                float y0 = __shfl_xor_sync(0xffffffffu, x0, 1);
                float y1 = __shfl_xor_sync(0xffffffffu, x1, 1);
                if ((lr & 1) == 0) {
                    int u = col >> 2;
                    float c = sigm(x1) * C0[(size_t)row * UU + u]
                            + sigm(x0) * tanhf(y0);
                    float h = sigm(y1) * tanhf(c);   // |h|<1, clip no-op
                    xo[(size_t)row * XON + u] = __float2half_rn(h);
                }
            }
        }
    }
}

// ---------------- fp16 mma.sync GEMM (3-stage, BK=32) for small GEMMs -----
template<int BM, int BN, int WM, int WN, int MT, int NT, typename OutT>
__global__ __launch_bounds__(WM * WN * 32, 2)
void hgemm(const __half* __restrict__ A, const __half* __restrict__ Bt,
           const float* __restrict__ bias, OutT* __restrict__ C,
           int Kdim, int lda, int ldb, int ldc, int Nreal, float clipv)
{
    constexpr int THREADS = WM * WN * 32;
    extern __shared__ __half sh[];
    __half* AsB = sh;
    __half* BsB = sh + 3 * BM * 40;

    const int tid  = threadIdx.x;
    const int lane = tid & 31;
    const int warp = tid >> 5;
    const int wm = warp / WN;
    const int wn = warp % WN;
    const int brow = blockIdx.y * BM;
    const int bcol = blockIdx.x * BN;
    const int lq = lane >> 2;
    const int lr = lane & 3;

    const __half* Ablk = A + (size_t)brow * lda;
    const __half* Bblk = Bt + (size_t)bcol * ldb;

    float acc[MT][NT][4];
    #pragma unroll
    for (int i = 0; i < MT; i++)
        #pragma unroll
        for (int j = 0; j < NT; j++)
            #pragma unroll
            for (int t = 0; t < 4; t++) acc[i][j][t] = 0.f;

    const int a_row = (lane & 7) + ((lane >> 3) & 1) * 8;
    const int a_ch  = (lane >> 4) * 8;
    const int b_row = ((lane >> 4) & 1) * 8 + (lane & 7);
    const int b_ch  = ((lane >> 3) & 1) * 8;

    const int KT = Kdim / 32;

    auto loadTile = [&](int buf, int k0) {
        __half* as = AsB + buf * BM * 40;
        __half* bs = BsB + buf * BN * 40;
        #pragma unroll
        for (int i = 0; i < (BM * 4) / THREADS; i++) {
            int ch = tid + i * THREADS;
            int r = ch >> 2, co = (ch & 3) * 8;
            cpasync16p(&as[r * 40 + co], Ablk + (size_t)r * lda + k0 + co);
        }
        #pragma unroll
        for (int i = 0; i < (BN * 4) / THREADS; i++) {
            int ch = tid + i * THREADS;
            int r = ch >> 2, co = (ch & 3) * 8;
            cpasync16p(&bs[r * 40 + co], Bblk + (size_t)r * ldb + k0 + co);
        }
        cpasync_commit();
    };

    auto computeTile = [&](int buf) {
        const __half* as = AsB + buf * BM * 40;
        const __half* bs = BsB + buf * BN * 40;
        #pragma unroll
        for (int kk = 0; kk < 2; kk++) {
            uint32_t af[MT][4];
            #pragma unroll
            for (int mt = 0; mt < MT; mt++) {
                int row = wm * (MT * 16) + mt * 16 + a_row;
                ldsm4(af[mt][0], af[mt][1], af[mt][2], af[mt][3],
                      as + row * 40 + kk * 16 + a_ch);
            }
            uint32_t bf[NT][2];
            #pragma unroll
            for (int p = 0; p < NT / 2; p++) {
                int row = wn * (NT * 8) + p * 16 + b_row;
                ldsm4(bf[2 * p][0], bf[2 * p][1], bf[2 * p + 1][0], bf[2 * p + 1][1],
                      bs + row * 40 + kk * 16 + b_ch);
            }
            #pragma unroll
            for (int mt = 0; mt < MT; mt++)
                #pragma unroll
                for (int nt = 0; nt < NT; nt++)
                    mma16816(acc[mt][nt], af[mt], bf[nt][0], bf[nt][1]);
        }
    };

    loadTile(0, 0);
    if (KT > 1) loadTile(1, 32); else cpasync_commit();
    for (int kt = 0; kt < KT; kt++) {
        cpasync_wait<1>();
        __syncthreads();
        computeTile(kt % 3);
        int nk = kt + 2;
        if (nk < KT) loadTile(nk % 3, nk * 32); else cpasync_commit();
    }

    #pragma unroll
    for (int mt = 0; mt < MT; mt++) {
        #pragma unroll
        for (int hh = 0; hh < 2; hh++) {
            int row = brow + wm * (MT * 16) + mt * 16 + lq + hh * 8;
            #pragma unroll
            for (int nt = 0; nt < NT; nt++) {
                int col = bcol + wn * (NT * 8) + nt * 8 + lr * 2;
                if (col < Nreal) {
                    float v0 = acc[mt][nt][hh * 2 + 0] + bias[col];
                    float v1 = acc[mt][nt][hh * 2 + 1] + bias[col + 1];
                    if (clipv > 0.f) {
                        v0 = fminf(fmaxf(v0, -clipv), clipv);
                        v1 = fminf(fmaxf(v1, -clipv), clipv);
                    }
                    if (sizeof(OutT) == 2) {
                        *(__half2*)((__half*)C + (size_t)row * ldc + col) =
                            __halves2half2(__float2half_rn(v0), __float2half_rn(v1));
                    } else {
                        *(float2*)((float*)C + (size_t)row * ldc + col) =
                            make_float2(v0, v1);
                    }
                }
            }
        }
    }
}

// ---------------- fused transpose prep ----------------
__device__ __forceinline__ void doTrans(float (*tl)[33],
    const float* __restrict__ src, __half* __restrict__ dst,
    int R, int C, int ld, int kOff, int gx, int rem, bool perm)
{
    int bx = rem % gx, by = rem / gx;
    int cb = bx * 32, rb = by * 32;
    int x = threadIdx.x & 31, y = threadIdx.x >> 5;
    #pragma unroll
    for (int i = 0; i < 32; i += 8) {
        int r = rb + y + i, c = cb + x;
        tl[y + i][x] = (r < R && c < C) ? src[(size_t)r * C + c] : 0.f;
    }
    __syncthreads();
    #pragma unroll
    for (int i = 0; i < 32; i += 8) {
        int c = cb + y + i, r = rb + x;
        if (c < C && r < R) {
            int cr = perm ? (4 * (c & 511) + (c >> 9)) : c;
            dst[(size_t)cr * ld + kOff + r] = __float2half(tl[x][y + i]);
        }
    }
}

__global__ __launch_bounds__(256)
void prep_transpose(const float* __restrict__ Wx, const float* __restrict__ Wh,
                    const float* __restrict__ Wprep, const float* __restrict__ Wr,
                    const float* __restrict__ Ww, const float* __restrict__ Wo)
{
    __shared__ float tl[32][33];
    int bid = blockIdx.x;
    if (bid < 1088)      doTrans(tl, Wx, g_wcat_t, 522, 2048, K2, 0,   64, bid, true);
    else if (bid < 2112) doTrans(tl, Wh, g_wcat_t, 512, 2048, K2, 522, 64, bid - 1088, true);
    else if (bid < 2144) doTrans(tl, Wprep, g_wprep_t, 64, 512, MM, 0, 16, bid - 2112, false);
    else if (bid < 2192) doTrans(tl, Wr, g_wrw_t, 512, 70, UU, 0, 3, bid - 2144, false);
    else if (bid < 2304) doTrans(tl, Ww, g_wrw_t + 70 * UU, 512, 198, UU, 0, 7, bid - 2192, false);
    else                 doTrans(tl, Wo, g_wo_t, 576, 512, XON, 0, 16, bid - 2304, false);
}

// ---------------- fused elementwise prep ----------------
#define EN0 (BB * K2)
#define EN1 (BB * MM)
#define EN2 ZN
#define EN3 RWNPAD
#define EN4 (ZN * (K2 - 1034))
#define EN5 ((RWNPAD - RWN) * UU)
#define ETOT (EN0 + EN1 + EN2 + EN3 + EN4 + EN5)

__global__ __launch_bounds__(256)
void prep_elem(const float* __restrict__ x_t, const float* __restrict__ H0,
               const float* __restrict__ R0, const float* __restrict__ br,
               const float* __restrict__ bw, const float* __restrict__ bl)
{
    int idx = blockIdx.x * 256 + threadIdx.x;
    if (idx < EN0) {
        int b = idx / K2, c = idx % K2;
        if (c < INP)                   g_xcat[idx] = __float2half(x_t[b * INP + c]);
        else if (c >= 522 && c < 1034) g_xcat[idx] = __float2half(H0[(size_t)b * UU + (c - 522)]);
        else if (c >= 1034)            g_xcat[idx] = __ushort_as_half(0);
        return;
    }
    idx -= EN0;
    if (idx < EN1) { g_r0h[idx] = __float2half(R0[idx]); return; }
    idx -= EN1;
    if (idx < EN2) {
        int u = idx >> 2, gate = idx & 3;
        g_blperm[idx] = bl[gate * UU + u];
        return;
    }
    idx -= EN2;
    if (idx < EN3) {
        float bv = 0.f;
        if (idx < 70) bv = br[idx];
        else if (idx < RWN) bv = bw[idx - 70];
        g_brw[idx] = bv;
        return;
    }
    idx -= EN3;
    if (idx < EN4) {
        const int L = K2 - 1034;
        int n = idx / L, c = idx % L;
        g_wcat_t[(size_t)n * K2 + 1034 + c] = __ushort_as_half(0);
        return;
    }
    idx -= EN4;
    if (idx < EN5) {
        g_wrw_t[(size_t)RWN * UU + idx] = __ushort_as_half(0);
        return;
    }
}

// ---------------- NTM addressing + memory update ----------------
#define ADDR_SMEM_FLOATS (16640 + 256 + 64 + 256 + 256 + 256 + 64 + 64 + 32 + 8)

__global__ __launch_bounds__(256)
void ntm_addr_kernel(const float* __restrict__ m0, const float* __restrict__ A0,
                     float* __restrict__ out_mt, float* __restrict__ out_Rt,
                     float* __restrict__ out_wr, float* __restrict__ out_ww,
                     __half* __restrict__ xo)
{
    extern __shared__ float sm[];
    float* m0s    = sm;
    float* mnorm  = sm + 16640;
    float* ks     = mnorm + 256;
    float* wgs    = ks + 64;
    float* wread  = wgs + 256;
    float* wwrite = wread + 256;
    float* delv   = wwrite + 256;
    float* addv   = delv + 64;
    float* red    = addv + 64;
    float* scal   = red + 32;

    const int b = blockIdx.x;
    const int tid = threadIdx.x;
    const float4* m0g4 = (const float4*)(m0 + (size_t)b * (NN * MM));

    #pragma unroll 4
    for (int e4 = tid; e4 < NN * MM / 4; e4 += 256) {
        float4 v = m0g4[e4];
        int n = e4 >> 4, m = (e4 & 15) * 4;
        float* p = &m0s[n * 65 + m];
        p[0] = v.x; p[1] = v.y; p[2] = v.z; p[3] = v.w;
    }
    __syncthreads();

    {
        float s = 0.f;
        #pragma unroll 8
        for (int m = 0; m < MM; m++) { float v = m0s[tid * 65 + m]; s += v * v; }
        mnorm[tid] = sqrtf(s);
    }

    const float* rwrow = g_rw + (size_t)b * RWN;

    for (int hd = 0; hd < 2; hd++) {
        const float* head = rwrow + (hd ? 70 : 0);
        if (tid < 64) ks[tid] = tanhf(head[tid]);
        if (tid == 64) {
            scal[0] = softplus(head[64]);
            scal[1] = sigm(head[65]);
            float a = head[66], bq = head[67], cq = head[68];
            float mx = fmaxf(a, fmaxf(bq, cq));
            float e0 = expf(a - mx), e1 = expf(bq - mx), e2 = expf(cq - mx);
            float se = e0 + e1 + e2;
            scal[2] = e0 / se; scal[3] = e1 / se; scal[4] = e2 / se;
            scal[5] = softplus(head[69]);
        }
        __syncthreads();

        float kv = (tid < 64) ? ks[tid] : 0.f;
        float knorm = sqrtf(blockReduceSum(kv * kv, red));

        float ip = 0.f;
        #pragma unroll 8
        for (int m = 0; m < MM; m++) ip += m0s[tid * 65 + m] * ks[m];
        float Kv = ip / (knorm * mnorm[tid] + 1e-8f);
        float x = scal[0] * Kv;
        float mx = blockReduceMax(x, red);
        float p = expf(x - mx);
        float sump = blockReduceSum(p, red);
        float wc = p / sump;

        float gg = scal[1];
        float wgv = gg * wc + (1.f - gg) * A0[(size_t)hd * BB * NN + (size_t)b * NN + tid];
        wgs[tid] = wgv;
        __syncthreads();

        float s0 = scal[2], s1 = scal[3], s2 = scal[4], gamma = scal[5];
        float conv = s0 * wgv + s1 * wgs[(tid + 255) & 255] + s2 * wgs[(tid + 1) & 255];
        float wsh = powf(conv, gamma);
        float ssum = blockReduceSum(wsh, red);
        float w = wsh / ssum;

        float* dst = hd ? wwrite : wread;
        dst[tid] = w;
        (hd ? out_ww : out_wr)[(size_t)b * NN + tid] = w;
        __syncthreads();
    }

    if (tid < 64) {
        delv[tid] = sigm(rwrow[140 + tid]);
        addv[tid] = tanhf(rwrow[204 + tid]);
    }

    {
        int q = tid >> 6, m = tid & 63;
        float s = 0.f;
        #pragma unroll 8
        for (int n = q * 64; n < q * 64 + 64; n++) s += wread[n] * m0s[n * 65 + m];
        wgs[tid] = s;
    }
    __syncthreads();
    if (tid < 64) {
        float r = wgs[tid] + wgs[64 + tid] + wgs[128 + tid] + wgs[192 + tid];
        out_Rt[(size_t)b * MM + tid] = r;
        xo[(size_t)b * XON + UU + tid] = __float2half(r);
    }

    float4* mt4 = (float4*)(out_mt + (size_t)b * (NN * MM));
    #pragma unroll 4
    for (int e4 = tid; e4 < NN * MM / 4; e4 += 256) {
        int n = e4 >> 4, m = (e4 & 15) * 4;
        float ww = wwrite[n];
        const float* p = &m0s[n * 65 + m];
        float4 v;
        v.x = p[0] * (1.f - ww * delv[m + 0]) + ww * addv[m + 0];
        v.y = p[1] * (1.f - ww * delv[m + 1]) + ww * addv[m + 1];
        v.z = p[2] * (1.f - ww * delv[m + 2]) + ww * addv[m + 2];
        v.w = p[3] * (1.f - ww * delv[m + 3]) + ww * addv[m + 3];
        mt4[e4] = v;
    }
}

// ---------------- launch ----------------
extern "C" void kernel_launch(void* const* d_in, const int* in_sizes, int n_in,
                              void* d_out, int out_size)
{
    const float* x_t   = (const float*)d_in[0];
    const float* H0    = (const float*)d_in[1];
    const float* C0    = (const float*)d_in[2];
    const float* m0    = (const float*)d_in[3];
    const float* R0    = (const float*)d_in[4];
    const float* A0    = (const float*)d_in[5];
    const float* Wprep = (const float*)d_in[6];
    const float* bprep = (const float*)d_in[7];
    const float* Wx    = (const float*)d_in[8];
    const float* Wh    = (const float*)d_in[9];
    const float* bl    = (const float*)d_in[10];
    const float* Wr    = (const float*)d_in[11];
    const float* br    = (const float*)d_in[12];
    const float* Ww    = (const float*)d_in[13];
    const float* bw    = (const float*)d_in[14];
    const float* Wo    = (const float*)d_in[15];
    const float* bo    = (const float*)d_in[16];

    float* out = (float*)d_out;
    float* y  = out;
    float* mt = y + (size_t)BB * UU;
    float* Rt = mt + (size_t)BB * NN * MM;
    float* wr = Rt + (size_t)BB * MM;
    float* ww = wr + (size_t)BB * NN;

    __half *xcat, *wcat_t, *wrw_t, *xo, *wo_t, *wprep_t, *r0h;
    float *blperm, *brw, *rw;
    cudaGetSymbolAddress((void**)&xcat, g_xcat);
    cudaGetSymbolAddress((void**)&wcat_t, g_wcat_t);
    cudaGetSymbolAddress((void**)&blperm, g_blperm);
    cudaGetSymbolAddress((void**)&wrw_t, g_wrw_t);
    cudaGetSymbolAddress((void**)&brw, g_brw);
    cudaGetSymbolAddress((void**)&rw, g_rw);
    cudaGetSymbolAddress((void**)&xo, g_xo);
    cudaGetSymbolAddress((void**)&wo_t, g_wo_t);
    cudaGetSymbolAddress((void**)&wprep_t, g_wprep_t);
    cudaGetSymbolAddress((void**)&r0h, g_r0h);

    const int SM_64 = 3 * (64 + 64) * 40 * (int)sizeof(__half);
    cudaFuncSetAttribute(hgemm_gates,
        cudaFuncAttributeMaxDynamicSharedMemorySize, G_SMEM);
    cudaFuncSetAttribute(hgemm<64, 64, 2, 2, 2, 4, __half>,
        cudaFuncAttributeMaxDynamicSharedMemorySize, SM_64);
    cudaFuncSetAttribute(hgemm<64, 64, 2, 2, 2, 4, float>,
        cudaFuncAttributeMaxDynamicSharedMemorySize, SM_64);

    // 1) weight transposes (gate-interleaved wcat)
    prep_transpose<<<2592, 256>>>(Wx, Wh, Wprep, Wr, Ww, Wo);

    // 2) elementwise prep
    prep_elem<<<(ETOT + 255) / 256, 256>>>(x_t, H0, R0, br, bw, bl);

    // 3) h_prep -> xcat cols [10,522)
    hgemm<64, 64, 2, 2, 2, 4, __half><<<dim3(UU / 64, BB / 64), 128, SM_64>>>(
        r0h, wprep_t, bprep, xcat + INP, 64, MM, MM, K2, UU, 0.f);

    // 4) z GEMM (BK=64 pipeline) + fused LSTM gates -> h into xo cols [0,512)
    hgemm_gates<<<dim3(ZN / 128, BB / 128), 256, G_SMEM>>>(
        xcat, wcat_t, blperm, C0, xo);

    // 5) [r_out | w_out] = h @ [Wr | Ww]
    hgemm<64, 64, 2, 2, 2, 4, float><<<dim3(RWNPAD / 64, BB / 64), 128, SM_64>>>(
        xo, wrw_t, brw, rw, UU, XON, UU, RWN, RWN, 0.f);

    // 6) addressing + memory update
    {
        size_t smem = ADDR_SMEM_FLOATS * sizeof(float);
        cudaFuncSetAttribute(ntm_addr_kernel,
                             cudaFuncAttributeMaxDynamicSharedMemorySize, (int)smem);
        ntm_addr_kernel<<<BB, 256, smem>>>(m0, A0, mt, Rt, wr, ww, xo);
    }

    // 7) y = [h | R_t] @ Wo + bo, clipped
    hgemm<64, 64, 2, 2, 2, 4, float><<<dim3(UU / 64, BB / 64), 128, SM_64>>>(
        xo, wo_t, bo, y, XON, XON, XON, UU, UU, CLIPV);
}